// round 3
// baseline (speedup 1.0000x reference)
#include <cuda_runtime.h>
#include <math.h>

#define NB 2
#define LB 512
#define FB 128
#define CB 64
#define HB 12
#define DB 16
#define NL (NB*LB)               // 1024
#define QKV (HB*DB)              // 192
#define FEAT (HB*CB + HB*DB + HB*7)  // 1044
#define TJ 64
#define NTILES (LB/TJ)           // 8
#define INFV 100000.0f
#define SQ29V 0.47140452079103173f
#define SCALEV 0.57735026918962576f

__device__ float g_q[NL*QKV];
__device__ float g_k[NL*QKV];
__device__ float g_v[NL*QKV];
__device__ int   g_mask[NL];
__device__ float g_feats[(size_t)NL*FEAT];

// ---------------------------------------------------------------------------
// Kernel A: decode the mask input whose serialized dtype (bool / int32 /
// float32) is ambiguous. Detect by byte pattern in the first 1024 bytes
// (safe to read for every candidate dtype: bool buffer is exactly 1024 B).
//   bool   : bytes at all offset%4 classes can be nonzero
//   int32  : nonzero only at offset%4==0 (LE low byte of 0/1)
//   float32: nonzero only at offset%4==3 (0x3f80_0000 high byte)
// ---------------------------------------------------------------------------
__global__ void decode_mask_kernel(const void* __restrict__ mraw) {
    __shared__ int cnt[4];
    int t = threadIdx.x;
    if (t < 4) cnt[t] = 0;
    __syncthreads();
    const unsigned char* b = (const unsigned char*)mraw;
    unsigned char v = b[t];
    if (v) atomicAdd(&cnt[t & 3], 1);
    __syncthreads();
    int m;
    if (cnt[1] | cnt[2] | cnt[3]) {
        if (cnt[0]) m = (b[t] != 0);                          // bool bytes
        else        m = (((const float*)mraw)[t] != 0.0f);    // float32
    } else {
        // only aligned low bytes nonzero (or everything zero) -> int32 view
        if (cnt[0]) m = (((const int*)mraw)[t] != 0);
        else        m = 0;  // all sampled bytes zero -> mask false
    }
    g_mask[t] = m;
}

// ---------------------------------------------------------------------------
// Kernel B: QKV projection. 8 rows per block; 576 threads = 3 mats x 192 out.
// ---------------------------------------------------------------------------
__global__ __launch_bounds__(576) void qkv_kernel(
    const float* __restrict__ x,
    const float* __restrict__ Wq,
    const float* __restrict__ Wk,
    const float* __restrict__ Wv)
{
    __shared__ float xs[8][FB];
    int t = threadIdx.x;
    int r0 = blockIdx.x * 8;
    for (int idx = t; idx < 8*FB; idx += 576)
        xs[idx >> 7][idx & 127] = x[(size_t)r0*FB + idx];
    __syncthreads();

    int which = t / QKV;        // 0:q 1:k 2:v
    int o = t - which*QKV;
    const float* W = (which == 0) ? Wq : (which == 1) ? Wk : Wv;
    float* outp    = (which == 0) ? g_q : (which == 1) ? g_k : g_v;
    const float4* W4 = (const float4*)(W + (size_t)o*FB);

    float acc[8];
#pragma unroll
    for (int r = 0; r < 8; r++) acc[r] = 0.f;

    for (int kk = 0; kk < FB/4; kk++) {
        float4 w = __ldg(&W4[kk]);
#pragma unroll
        for (int r = 0; r < 8; r++) {
            float4 xv = *(const float4*)&xs[r][kk*4];
            acc[r] += w.x*xv.x + w.y*xv.y + w.z*xv.z + w.w*xv.w;
        }
    }
#pragma unroll
    for (int r = 0; r < 8; r++)
        outp[(size_t)(r0 + r)*QKV + o] = acc[r];
}

// ---------------------------------------------------------------------------
// Kernel C: fused flash attention over j for one (n,i) per block.
// Reads z exactly once. Online softmax with running max/sum per head.
// Produces the 1044-wide concat feature vector in g_feats.
// ---------------------------------------------------------------------------
__global__ __launch_bounds__(256) void attn_kernel(
    const float* __restrict__ R,
    const float* __restrict__ tvec,
    const float* __restrict__ pCB,
    const float* __restrict__ z,
    const float* __restrict__ Wpb,
    const float* __restrict__ gamma_raw)
{
    const int ni = blockIdx.x;
    const int n = ni / LB;
    const int t = threadIdx.x;

    __shared__ float qs[QKV];
    __shared__ float WpbT[CB*HB];      // transposed [c][h] -> conflict-free
    __shared__ float zs[TJ*CB];        // [j][c]
    __shared__ float lg[TJ*HB];        // logits then p, [j][h]
    __shared__ float pmax[HB*16];      // partial maxes [h][seg]
    __shared__ float d2s[TJ];
    __shared__ float pjs[TJ*4];
    __shared__ float mfac[TJ];
    __shared__ float mhead[HB], shead[HB], scaleF[HB], invH[HB], coefH[HB];
    __shared__ float accZ[HB*CB];      // [h][c]
    __shared__ float accV[HB*DB];      // [h][d]
    __shared__ float accP[HB*4];       // [h][3] padded
    __shared__ float pci[3];
    __shared__ int rowValid;

    // ---- init ----
    if (t < QKV) qs[t] = g_q[(size_t)ni*QKV + t];
    for (int o = t; o < HB*CB; o += 256) {
        int h = o / CB, c = o - h*CB;
        WpbT[c*HB + h] = Wpb[o];
    }
    for (int o = t; o < HB*CB; o += 256) accZ[o] = 0.f;
    if (t < HB*DB) accV[t] = 0.f;
    if (t < HB*4)  accP[t] = 0.f;
    if (t < HB) {
        float g = gamma_raw[t];
        float sp = log1pf(__expf(g));             // softplus
        coefH[t] = -sp * SQ29V * 0.5f;
        mhead[t] = -INFINITY;
        shead[t] = 0.f;
    }
    if (t < 3) pci[t] = pCB[(size_t)ni*3 + t];
    if (t == 0) rowValid = g_mask[ni];
    __syncthreads();

    const size_t zrow = (size_t)ni * LB * CB;

    for (int jt = 0; jt < NTILES; jt++) {
        const int j0 = jt * TJ;

        // stage 1: load z tile (contiguous 4096 floats)
        {
            const float4* zg = (const float4*)(z + zrow + (size_t)j0*CB);
            float4* zs4 = (float4*)zs;
#pragma unroll
            for (int r = 0; r < 4; r++)
                zs4[t + 256*r] = __ldg(&zg[t + 256*r]);
        }
        // stage 2: d2, neighbor positions, additive mask
        if (t < TJ) {
            int j = j0 + t;
            const float* pj = pCB + (size_t)(n*LB + j)*3;
            float px = pj[0], py = pj[1], pz = pj[2];
            pjs[t*4+0] = px; pjs[t*4+1] = py; pjs[t*4+2] = pz;
            float dx = px - pci[0], dy = py - pci[1], dz = pz - pci[2];
            d2s[t] = dx*dx + dy*dy + dz*dz;
            mfac[t] = (rowValid && g_mask[n*LB + j]) ? 0.f : -INFV;
        }
        __syncthreads();

        // stage 3: logits for the tile: (node + pair + beta)*SCALE + mask
#pragma unroll
        for (int r = 0; r < 3; r++) {
            int item = t + 256*r;                 // item == j*HB + h
            int j = item / HB, h = item - j*HB;
            const float4* kp = (const float4*)(g_k + (size_t)(n*LB + j0 + j)*QKV + h*DB);
            const float4* qp = (const float4*)(qs + h*DB);
            float acc = 0.f;
#pragma unroll
            for (int m4 = 0; m4 < 4; m4++) {
                float4 kv = __ldg(&kp[m4]);
                float4 qv = qp[m4];
                acc += kv.x*qv.x + kv.y*qv.y + kv.z*qv.z + kv.w*qv.w;
            }
            const float4* z4 = (const float4*)(zs + j*CB);
            const float* wc = WpbT + h;
#pragma unroll
            for (int c4 = 0; c4 < CB/4; c4++) {
                float4 zv = z4[c4];
                acc += zv.x*wc[(c4*4+0)*HB] + zv.y*wc[(c4*4+1)*HB]
                     + zv.z*wc[(c4*4+2)*HB] + zv.w*wc[(c4*4+3)*HB];
            }
            acc += coefH[h] * d2s[j];
            lg[item] = acc * SCALEV + mfac[j];
        }
        __syncthreads();

        // stage 4a: partial per-head max (192 threads, 4 j each)
        if (t < 192) {
            int h = t % HB, seg = t / HB;         // seg 0..15, j = seg*4..seg*4+3
            float tm = lg[(seg*4+0)*HB + h];
            tm = fmaxf(tm, lg[(seg*4+1)*HB + h]);
            tm = fmaxf(tm, lg[(seg*4+2)*HB + h]);
            tm = fmaxf(tm, lg[(seg*4+3)*HB + h]);
            pmax[h*16 + seg] = tm;
        }
        __syncthreads();
        // stage 4b: combine + rescale factor
        if (t < HB) {
            float tm = pmax[t*16];
#pragma unroll
            for (int s = 1; s < 16; s++) tm = fmaxf(tm, pmax[t*16 + s]);
            float nm = fmaxf(mhead[t], tm);
            scaleF[t] = __expf(mhead[t] - nm);    // exp(-inf)=0 on first tile
            mhead[t] = nm;
        }
        __syncthreads();

        // stage 5: p = exp(lg - m); rescale accumulators
#pragma unroll
        for (int r = 0; r < 3; r++) {
            int item = t + 256*r;
            int h = item % HB;
            lg[item] = __expf(lg[item] - mhead[h]);
        }
        for (int o = t; o < HB*CB; o += 256) accZ[o] *= scaleF[o / CB];
        if (t < HB*DB) accV[t] *= scaleF[t / DB];
        if (t < HB*4)  accP[t] *= scaleF[t >> 2];
        __syncthreads();

        // stage 6: accumulate p·z (192 threads), p·v / p·pCB / sum p (64 threads)
        if (t < 192) {
            int h = t >> 4, cg = t & 15;
            float4* aZ = (float4*)(accZ + h*CB) + cg;
            float4 a = *aZ;
            const float* pcol = lg + h;
            const float4* zc = (const float4*)zs + cg;
#pragma unroll 4
            for (int j = 0; j < TJ; j++) {
                float p = pcol[j*HB];
                float4 zv = zc[j*16];
                a.x += p*zv.x; a.y += p*zv.y; a.z += p*zv.z; a.w += p*zv.w;
            }
            *aZ = a;
        } else {
            int tc = t - 192;                       // 0..63
            int h0 = tc / DB, h1 = (tc+64) / DB, h2 = (tc+128) / DB;
            const float* vb = g_v + (size_t)(n*LB + j0)*QKV;
            float a0 = 0.f, a1 = 0.f, a2 = 0.f;
#pragma unroll 2
            for (int j = 0; j < TJ; j++) {
                const float* vr = vb + j*QKV;
                float p0 = lg[j*HB + h0];
                float p1 = lg[j*HB + h1];
                float p2 = lg[j*HB + h2];
                a0 += p0 * __ldg(vr + tc);
                a1 += p1 * __ldg(vr + tc + 64);
                a2 += p2 * __ldg(vr + tc + 128);
            }
            accV[tc]      += a0;
            accV[tc + 64] += a1;
            accV[tc + 128]+= a2;
            if (tc < HB*3) {                        // aggr += p * p_CB
                int h = tc / 3, cc = tc - h*3;
                float a = 0.f;
                for (int j = 0; j < TJ; j++) a += lg[j*HB + h] * pjs[j*4 + cc];
                accP[h*4 + cc] += a;
            } else if (tc < HB*3 + HB) {            // running sum
                int h = tc - HB*3;
                float s = 0.f;
                for (int j = 0; j < TJ; j++) s += lg[j*HB + h];
                shead[h] = shead[h]*scaleF[h] + s;
            }
        }
        __syncthreads();
    }

    // ---- finalize: normalize and emit 1044 features ----
    if (t < HB) invH[t] = rowValid ? (1.0f / shead[t]) : 0.f;
    __syncthreads();

    float* fo = g_feats + (size_t)ni*FEAT;
    for (int o = t; o < HB*CB; o += 256) fo[o] = accZ[o] * invH[o / CB];         // feat_p2n
    if (t < HB*DB) fo[HB*CB + t] = accV[t] * invH[t / DB];                        // feat_node
    if (t < HB) {
        int h = t;
        float inv = invH[h];
        float a0 = accP[h*4+0]*inv - tvec[(size_t)ni*3+0];
        float a1 = accP[h*4+1]*inv - tvec[(size_t)ni*3+1];
        float a2 = accP[h*4+2]*inv - tvec[(size_t)ni*3+2];
        const float* Rp = R + (size_t)ni*9;          // R[j][ic], local = R^T (a - t)
        float l0 = Rp[0]*a0 + Rp[3]*a1 + Rp[6]*a2;
        float l1 = Rp[1]*a0 + Rp[4]*a1 + Rp[7]*a2;
        float l2 = Rp[2]*a0 + Rp[5]*a1 + Rp[8]*a2;
        float dist = sqrtf(l0*l0 + l1*l1 + l2*l2);
        float idn = 1.0f / (dist + 1e-4f);
        const int b0 = HB*CB + HB*DB;                // 960
        fo[b0 + h*3 + 0] = l0;
        fo[b0 + h*3 + 1] = l1;
        fo[b0 + h*3 + 2] = l2;
        fo[b0 + 36 + h]  = dist;                     // 996..1007
        fo[b0 + 48 + h*3 + 0] = l0*idn;              // 1008..1043
        fo[b0 + 48 + h*3 + 1] = l1*idn;
        fo[b0 + 48 + h*3 + 2] = l2*idn;
    }
}

// ---------------------------------------------------------------------------
// Kernel D: output projection (16-row tile) + bias + row mask + residual + LN
// ---------------------------------------------------------------------------
__global__ __launch_bounds__(256) void out_kernel(
    const float* __restrict__ x,
    const float* __restrict__ Wout,
    const float* __restrict__ bout,
    const float* __restrict__ lnw,
    const float* __restrict__ lnb,
    float* __restrict__ out)
{
    __shared__ float fs[16][FEAT + 4];   // stride 1048 (float4-aligned)
    __shared__ float ys[16][FB];
    int t = threadIdx.x;
    int r0 = blockIdx.x * 16;

    for (int r = 0; r < 16; r++)
        for (int o = t; o < FEAT; o += 256)
            fs[r][o] = g_feats[(size_t)(r0 + r)*FEAT + o];
    __syncthreads();

    int f = t & 127, rg = t >> 7;        // rg selects rows rg*8 .. rg*8+7
    float acc[8];
#pragma unroll
    for (int r = 0; r < 8; r++) acc[r] = 0.f;

    const float4* W4 = (const float4*)(Wout + (size_t)f*FEAT);
    for (int k4 = 0; k4 < FEAT/4; k4++) {
        float4 w = __ldg(&W4[k4]);
#pragma unroll
        for (int r = 0; r < 8; r++) {
            float4 fv = *(const float4*)&fs[rg*8 + r][k4*4];
            acc[r] += w.x*fv.x + w.y*fv.y + w.z*fv.z + w.w*fv.w;
        }
    }

    float bv = bout[f];
#pragma unroll
    for (int r = 0; r < 8; r++) {
        int row = rg*8 + r;
        int ri = r0 + row;
        float xv = x[(size_t)ri*FB + f];
        float val = g_mask[ri] ? (acc[r] + bv) : 0.f;
        ys[row][f] = xv + val;
    }
    __syncthreads();

    // LayerNorm: each warp handles 2 rows
    int wid = t >> 5, lane = t & 31;
#pragma unroll
    for (int rr = 0; rr < 2; rr++) {
        int row = wid*2 + rr;
        float v0 = ys[row][lane], v1 = ys[row][lane+32];
        float v2 = ys[row][lane+64], v3 = ys[row][lane+96];
        float s = v0 + v1 + v2 + v3;
#pragma unroll
        for (int off = 16; off; off >>= 1) s += __shfl_xor_sync(0xffffffffu, s, off);
        float mu = s * (1.0f/128.0f);
        float d0 = v0-mu, d1 = v1-mu, d2 = v2-mu, d3 = v3-mu;
        float sq = d0*d0 + d1*d1 + d2*d2 + d3*d3;
#pragma unroll
        for (int off = 16; off; off >>= 1) sq += __shfl_xor_sync(0xffffffffu, sq, off);
        float rstd = rsqrtf(sq * (1.0f/128.0f) + 1e-5f);
        int ri = r0 + row;
        out[(size_t)ri*FB + lane     ] = d0*rstd*lnw[lane     ] + lnb[lane     ];
        out[(size_t)ri*FB + lane + 32] = d1*rstd*lnw[lane + 32] + lnb[lane + 32];
        out[(size_t)ri*FB + lane + 64] = d2*rstd*lnw[lane + 64] + lnb[lane + 64];
        out[(size_t)ri*FB + lane + 96] = d3*rstd*lnw[lane + 96] + lnb[lane + 96];
    }
}

extern "C" void kernel_launch(void* const* d_in, const int* in_sizes, int n_in,
                              void* d_out, int out_size) {
    const float* R    = (const float*)d_in[0];
    const float* tv   = (const float*)d_in[1];
    const float* pCB  = (const float*)d_in[2];
    const float* x    = (const float*)d_in[3];
    const float* z    = (const float*)d_in[4];
    const void*  mask = d_in[5];
    const float* Wq   = (const float*)d_in[6];
    const float* Wk   = (const float*)d_in[7];
    const float* Wv   = (const float*)d_in[8];
    const float* Wpb  = (const float*)d_in[9];
    const float* gr   = (const float*)d_in[10];
    const float* Wout = (const float*)d_in[11];
    const float* bo   = (const float*)d_in[12];
    const float* lnw  = (const float*)d_in[13];
    const float* lnb  = (const float*)d_in[14];
    float* out = (float*)d_out;

    decode_mask_kernel<<<1, NL>>>(mask);
    qkv_kernel<<<NL/8, 576>>>(x, Wq, Wk, Wv);
    attn_kernel<<<NL, 256>>>(R, tv, pCB, z, Wpb, gr);
    out_kernel<<<NL/16, 256>>>(x, Wout, bo, lnw, lnb, out);
}

// round 5
// speedup vs baseline: 1.0607x; 1.0607x over previous
#include <cuda_runtime.h>
#include <math.h>

#define NB 2
#define LB 512
#define FB 128
#define CB 64
#define HB 12
#define DB 16
#define NL (NB*LB)               // 1024
#define QKV (HB*DB)              // 192
#define FEAT (HB*CB + HB*DB + HB*7)  // 1044
#define TJ 64
#define NTILES (LB/TJ)           // 8
#define INFV 100000.0f
#define SQ29V 0.47140452079103173f
#define SCALEV 0.57735026918962576f
#define ORPB 8                   // out_kernel rows per block

__device__ float g_q[NL*QKV];
__device__ float g_k[NL*QKV];
__device__ float g_vT[NB*QKV*LB];     // [n][hd][j]  (transposed v)
__device__ int   g_mask[NL];
__device__ float g_feats[(size_t)NL*FEAT];

__device__ __forceinline__ void cp_async16(void* smem_dst, const void* gmem_src) {
    unsigned s = (unsigned)__cvta_generic_to_shared(smem_dst);
    asm volatile("cp.async.cg.shared.global [%0], [%1], 16;\n" :: "r"(s), "l"(gmem_src));
}
#define CP_COMMIT() asm volatile("cp.async.commit_group;\n")
#define CP_WAIT1()  asm volatile("cp.async.wait_group 1;\n")
#define CP_WAIT0()  asm volatile("cp.async.wait_group 0;\n")

// ---------------------------------------------------------------------------
// Kernel A: decode mask input of ambiguous serialized dtype (bool/int32/fp32).
// ---------------------------------------------------------------------------
__global__ void decode_mask_kernel(const void* __restrict__ mraw) {
    __shared__ int cnt[4];
    int t = threadIdx.x;
    if (t < 4) cnt[t] = 0;
    __syncthreads();
    const unsigned char* b = (const unsigned char*)mraw;
    unsigned char v = b[t];
    if (v) atomicAdd(&cnt[t & 3], 1);
    __syncthreads();
    int m;
    if (cnt[1] | cnt[2] | cnt[3]) {
        if (cnt[0]) m = (b[t] != 0);                          // bool bytes
        else        m = (((const float*)mraw)[t] != 0.0f);    // float32
    } else {
        if (cnt[0]) m = (((const int*)mraw)[t] != 0);         // int32
        else        m = 0;
    }
    g_mask[t] = m;
}

// ---------------------------------------------------------------------------
// Kernel B: QKV projection. 8 rows/block; 576 threads = 3 mats x 192 outputs.
// v is written TRANSPOSED: g_vT[n][hd][j].
// ---------------------------------------------------------------------------
__global__ __launch_bounds__(576) void qkv_kernel(
    const float* __restrict__ x,
    const float* __restrict__ Wq,
    const float* __restrict__ Wk,
    const float* __restrict__ Wv)
{
    __shared__ float xs[8][FB];
    int t = threadIdx.x;
    int r0 = blockIdx.x * 8;
    for (int idx = t; idx < 8*FB; idx += 576)
        xs[idx >> 7][idx & 127] = x[(size_t)r0*FB + idx];
    __syncthreads();

    int which = t / QKV;        // 0:q 1:k 2:v
    int o = t - which*QKV;
    const float* W = (which == 0) ? Wq : (which == 1) ? Wk : Wv;
    const float4* W4 = (const float4*)(W + (size_t)o*FB);

    float acc[8];
#pragma unroll
    for (int r = 0; r < 8; r++) acc[r] = 0.f;

    for (int kk = 0; kk < FB/4; kk++) {
        float4 w = __ldg(&W4[kk]);
#pragma unroll
        for (int r = 0; r < 8; r++) {
            float4 xv = *(const float4*)&xs[r][kk*4];
            acc[r] += w.x*xv.x + w.y*xv.y + w.z*xv.z + w.w*xv.w;
        }
    }
    if (which == 2) {
        int n = r0 >> 9, jb = r0 & (LB-1);
        float* vp = g_vT + ((size_t)n*QKV + o)*LB + jb;
#pragma unroll
        for (int r = 0; r < 8; r++) vp[r] = acc[r];
    } else {
        float* outp = (which == 0) ? g_q : g_k;
#pragma unroll
        for (int r = 0; r < 8; r++)
            outp[(size_t)(r0 + r)*QKV + o] = acc[r];
    }
}

// ---------------------------------------------------------------------------
// Kernel C: fused flash attention over j for one (n,i) per block.
// z read exactly once via cp.async double-buffered tiles.
// ---------------------------------------------------------------------------
__global__ __launch_bounds__(256) void attn_kernel(
    const float* __restrict__ R,
    const float* __restrict__ tvec,
    const float* __restrict__ pCB,
    const float* __restrict__ z,
    const float* __restrict__ Wpb,
    const float* __restrict__ gamma_raw)
{
    const int ni = blockIdx.x;
    const int n = ni / LB;
    const int t = threadIdx.x;

    // dynamic smem: zs double buffer + per-j precomputed arrays
    extern __shared__ float sm[];
    float* zsb[2] = { sm, sm + TJ*CB };        // 2 x 4096
    float* d2s  = sm + 2*TJ*CB;                // 512
    float* mfac = d2s + LB;                    // 512

    __shared__ float qs[QKV];
    __shared__ float WpbT[CB*HB];
    __shared__ float lg[TJ*HB];
    __shared__ float pmax[HB*16];
    __shared__ float mhead[HB], shead[HB], scaleF[HB], invH[HB], coefH[HB];
    __shared__ float accZ[HB*CB];
    __shared__ float accV[HB*DB];
    __shared__ float accP[HB*4];
    __shared__ float pci[3];
    __shared__ int rowValid;

    const size_t zrow = (size_t)ni * LB * CB;

    // prefetch z tile 0
    {
        const float4* zg = (const float4*)(z + zrow);
        float4* dst = (float4*)zsb[0];
#pragma unroll
        for (int r = 0; r < 4; r++) cp_async16(dst + t + 256*r, zg + t + 256*r);
        CP_COMMIT();
    }

    // ---- init A ----
    if (t < QKV) qs[t] = g_q[(size_t)ni*QKV + t];
    for (int o = t; o < HB*CB; o += 256) {
        int h = o / CB, c = o - h*CB;
        WpbT[c*HB + h] = Wpb[o];
    }
    for (int o = t; o < HB*CB; o += 256) accZ[o] = 0.f;
    if (t < HB*DB) accV[t] = 0.f;
    if (t < HB*4)  accP[t] = 0.f;
    if (t < HB) {
        float g = gamma_raw[t];
        float sp = log1pf(__expf(g));             // softplus
        coefH[t] = -sp * SQ29V * 0.5f;
        mhead[t] = -INFINITY;
        shead[t] = 0.f;
    }
    if (t < 3) pci[t] = pCB[(size_t)ni*3 + t];
    if (t == 0) rowValid = g_mask[ni];
    __syncthreads();

    // ---- init B: per-j d2 and additive mask for ALL 512 j ----
    for (int j = t; j < LB; j += 256) {
        const float* pj = pCB + (size_t)(n*LB + j)*3;
        float dx = pj[0] - pci[0], dy = pj[1] - pci[1], dz = pj[2] - pci[2];
        d2s[j] = dx*dx + dy*dy + dz*dz;
        mfac[j] = (rowValid && g_mask[n*LB + j]) ? 0.f : -INFV;
    }
    // (no sync needed here: the post-wait sync in the loop orders init B)

    for (int jt = 0; jt < NTILES; jt++) {
        const int j0 = jt * TJ;
        const int buf = jt & 1;

        // prefetch next tile into the other buffer
        if (jt < NTILES-1) {
            const float4* zg = (const float4*)(z + zrow + (size_t)(j0+TJ)*CB);
            float4* dst = (float4*)zsb[buf^1];
#pragma unroll
            for (int r = 0; r < 4; r++) cp_async16(dst + t + 256*r, zg + t + 256*r);
            CP_COMMIT();
            CP_WAIT1();
        } else {
            CP_WAIT0();
        }
        __syncthreads();

        const float* zs = zsb[buf];

        // stage 3: logits (node + z·Wpb + beta·d2)*SCALE + mask
#pragma unroll
        for (int r = 0; r < 3; r++) {
            int item = t + 256*r;                 // item == j*HB + h
            int j = item / HB, h = item - j*HB;
            const float4* kp = (const float4*)(g_k + (size_t)(n*LB + j0 + j)*QKV + h*DB);
            const float4* qp = (const float4*)(qs + h*DB);
            float acc = 0.f;
#pragma unroll
            for (int m4 = 0; m4 < 4; m4++) {
                float4 kv = __ldg(&kp[m4]);
                float4 qv = qp[m4];
                acc += kv.x*qv.x + kv.y*qv.y + kv.z*qv.z + kv.w*qv.w;
            }
            const float4* z4 = (const float4*)(zs + j*CB);
            const float* wc = WpbT + h;
#pragma unroll
            for (int c4 = 0; c4 < CB/4; c4++) {
                float4 zv = z4[c4];
                acc += zv.x*wc[(c4*4+0)*HB] + zv.y*wc[(c4*4+1)*HB]
                     + zv.z*wc[(c4*4+2)*HB] + zv.w*wc[(c4*4+3)*HB];
            }
            acc += coefH[h] * d2s[j0 + j];
            lg[item] = acc * SCALEV + mfac[j0 + j];
        }
        __syncthreads();

        // stage 4a: partial per-head max (192 threads, 4 j each)
        if (t < 192) {
            int h = t % HB, seg = t / HB;
            float tm = lg[(seg*4+0)*HB + h];
            tm = fmaxf(tm, lg[(seg*4+1)*HB + h]);
            tm = fmaxf(tm, lg[(seg*4+2)*HB + h]);
            tm = fmaxf(tm, lg[(seg*4+3)*HB + h]);
            pmax[h*16 + seg] = tm;
        }
        __syncthreads();
        // stage 4b
        if (t < HB) {
            float tm = pmax[t*16];
#pragma unroll
            for (int s = 1; s < 16; s++) tm = fmaxf(tm, pmax[t*16 + s]);
            float nm = fmaxf(mhead[t], tm);
            scaleF[t] = __expf(mhead[t] - nm);
            mhead[t] = nm;
        }
        __syncthreads();

        // stage 5: p = exp(lg - m); rescale accumulators
#pragma unroll
        for (int r = 0; r < 3; r++) {
            int item = t + 256*r;
            int h = item % HB;
            lg[item] = __expf(lg[item] - mhead[h]);
        }
        for (int o = t; o < HB*CB; o += 256) accZ[o] *= scaleF[o / CB];
        if (t < HB*DB) accV[t] *= scaleF[t >> 4];
        if (t < HB*4)  accP[t] *= scaleF[t >> 2];
        __syncthreads();

        // stage 6
        if (t < 192) {
            // p·z : thread (h, cg) accumulates 4 c's over 64 j
            int h = t >> 4, cg = t & 15;
            float4* aZ = (float4*)(accZ + h*CB) + cg;
            float4 a = *aZ;
            const float* pcol = lg + h;
            const float4* zc = (const float4*)zs + cg;
#pragma unroll 4
            for (int j = 0; j < TJ; j++) {
                float p = pcol[j*HB];
                float4 zv = zc[j*16];
                a.x += p*zv.x; a.y += p*zv.y; a.z += p*zv.z; a.w += p*zv.w;
            }
            *aZ = a;
        } else {
            int tc = t - 192;                       // 0..63
            // p·v : 3 contiguous vT rows per thread
            const float* vbase = g_vT + (size_t)n*QKV*LB + j0;
            const float4* v0 = (const float4*)(vbase + (size_t)(tc      )*LB);
            const float4* v1 = (const float4*)(vbase + (size_t)(tc +  64)*LB);
            const float4* v2 = (const float4*)(vbase + (size_t)(tc + 128)*LB);
            int h0 = tc >> 4, h1 = (tc+64) >> 4, h2 = (tc+128) >> 4;
            float a0 = 0.f, a1 = 0.f, a2 = 0.f;
#pragma unroll 4
            for (int q4 = 0; q4 < TJ/4; q4++) {
                float4 x0 = __ldg(v0+q4), x1 = __ldg(v1+q4), x2 = __ldg(v2+q4);
                int j = q4*4;
                float p00=lg[(j+0)*HB+h0], p01=lg[(j+1)*HB+h0], p02=lg[(j+2)*HB+h0], p03=lg[(j+3)*HB+h0];
                a0 += x0.x*p00 + x0.y*p01 + x0.z*p02 + x0.w*p03;
                float p10=lg[(j+0)*HB+h1], p11=lg[(j+1)*HB+h1], p12=lg[(j+2)*HB+h1], p13=lg[(j+3)*HB+h1];
                a1 += x1.x*p10 + x1.y*p11 + x1.z*p12 + x1.w*p13;
                float p20=lg[(j+0)*HB+h2], p21=lg[(j+1)*HB+h2], p22=lg[(j+2)*HB+h2], p23=lg[(j+3)*HB+h2];
                a2 += x2.x*p20 + x2.y*p21 + x2.z*p22 + x2.w*p23;
            }
            accV[tc]       += a0;
            accV[tc +  64] += a1;
            accV[tc + 128] += a2;

            if (tc < HB*3) {                        // aggr += p * p_CB
                int h = tc / 3, cc = tc - h*3;
                const float* pb = pCB + (size_t)(n*LB + j0)*3 + cc;
                float a = 0.f;
                for (int j = 0; j < TJ; j++) a += lg[j*HB + h] * __ldg(pb + j*3);
                accP[h*4 + cc] += a;
            } else if (tc < HB*3 + HB) {            // running sum of p
                int h = tc - HB*3;
                float s = 0.f;
                for (int j = 0; j < TJ; j++) s += lg[j*HB + h];
                shead[h] = shead[h]*scaleF[h] + s;
            }
        }
        __syncthreads();
    }

    // ---- finalize ----
    if (t < HB) invH[t] = rowValid ? (1.0f / shead[t]) : 0.f;
    __syncthreads();

    float* fo = g_feats + (size_t)ni*FEAT;
    for (int o = t; o < HB*CB; o += 256) fo[o] = accZ[o] * invH[o / CB];
    if (t < HB*DB) fo[HB*CB + t] = accV[t] * invH[t >> 4];
    if (t < HB) {
        int h = t;
        float inv = invH[h];
        float a0 = accP[h*4+0]*inv - tvec[(size_t)ni*3+0];
        float a1 = accP[h*4+1]*inv - tvec[(size_t)ni*3+1];
        float a2 = accP[h*4+2]*inv - tvec[(size_t)ni*3+2];
        const float* Rp = R + (size_t)ni*9;          // local = R^T (a - t)
        float l0 = Rp[0]*a0 + Rp[3]*a1 + Rp[6]*a2;
        float l1 = Rp[1]*a0 + Rp[4]*a1 + Rp[7]*a2;
        float l2 = Rp[2]*a0 + Rp[5]*a1 + Rp[8]*a2;
        float dist = sqrtf(l0*l0 + l1*l1 + l2*l2);
        float idn = 1.0f / (dist + 1e-4f);
        const int b0 = HB*CB + HB*DB;                // 960
        fo[b0 + h*3 + 0] = l0;
        fo[b0 + h*3 + 1] = l1;
        fo[b0 + h*3 + 2] = l2;
        fo[b0 + 36 + h]  = dist;
        fo[b0 + 48 + h*3 + 0] = l0*idn;
        fo[b0 + 48 + h*3 + 1] = l1*idn;
        fo[b0 + 48 + h*3 + 2] = l2*idn;
    }
}

// ---------------------------------------------------------------------------
// Kernel D: output projection (8 rows, 2x2 register blocking) + residual + LN
// ---------------------------------------------------------------------------
__global__ __launch_bounds__(256) void out_kernel(
    const float* __restrict__ x,
    const float* __restrict__ Wout,
    const float* __restrict__ bout,
    const float* __restrict__ lnw,
    const float* __restrict__ lnb,
    float* __restrict__ out)
{
    __shared__ float fs[ORPB][FEAT + 4];   // row stride 1048 (16B aligned)
    __shared__ float ys[ORPB][FB];
    int t = threadIdx.x;
    int r0 = blockIdx.x * ORPB;

#pragma unroll
    for (int r = 0; r < ORPB; r++) {
        const float4* src = (const float4*)(g_feats + (size_t)(r0 + r)*FEAT);
        float4* d = (float4*)fs[r];
        for (int o = t; o < FEAT/4; o += 256) d[o] = src[o];
    }
    __syncthreads();

    int fg = t & 63, rg = t >> 6;          // f0 = fg*2, rows rg*2, rg*2+1
    int f0 = fg*2;
    float a00=0.f, a01=0.f, a10=0.f, a11=0.f;
    const float4* W0 = (const float4*)(Wout + (size_t)f0*FEAT);
    const float4* W1 = (const float4*)(Wout + (size_t)(f0+1)*FEAT);
    const float4* F0 = (const float4*)fs[rg*2];
    const float4* F1 = (const float4*)fs[rg*2 + 1];

    for (int k = 0; k < FEAT/4; k++) {
        float4 w0 = __ldg(&W0[k]);
        float4 w1 = __ldg(&W1[k]);
        float4 x0 = F0[k];
        float4 x1 = F1[k];
        a00 += w0.x*x0.x + w0.y*x0.y + w0.z*x0.z + w0.w*x0.w;
        a01 += w1.x*x0.x + w1.y*x0.y + w1.z*x0.z + w1.w*x0.w;
        a10 += w0.x*x1.x + w0.y*x1.y + w0.z*x1.z + w0.w*x1.w;
        a11 += w1.x*x1.x + w1.y*x1.y + w1.z*x1.z + w1.w*x1.w;
    }

    float b0 = bout[f0], b1 = bout[f0+1];
    int ri0 = r0 + rg*2, ri1 = ri0 + 1;
    int m0 = g_mask[ri0], m1 = g_mask[ri1];
    ys[rg*2  ][f0  ] = x[(size_t)ri0*FB + f0  ] + (m0 ? (a00 + b0) : 0.f);
    ys[rg*2  ][f0+1] = x[(size_t)ri0*FB + f0+1] + (m0 ? (a01 + b1) : 0.f);
    ys[rg*2+1][f0  ] = x[(size_t)ri1*FB + f0  ] + (m1 ? (a10 + b0) : 0.f);
    ys[rg*2+1][f0+1] = x[(size_t)ri1*FB + f0+1] + (m1 ? (a11 + b1) : 0.f);
    __syncthreads();

    // LayerNorm: one warp per row
    int wid = t >> 5, lane = t & 31;
    int row = wid;
    float v0 = ys[row][lane], v1 = ys[row][lane+32];
    float v2 = ys[row][lane+64], v3 = ys[row][lane+96];
    float s = v0 + v1 + v2 + v3;
#pragma unroll
    for (int off = 16; off; off >>= 1) s += __shfl_xor_sync(0xffffffffu, s, off);
    float mu = s * (1.0f/128.0f);
    float d0 = v0-mu, d1 = v1-mu, d2 = v2-mu, d3 = v3-mu;
    float sq = d0*d0 + d1*d1 + d2*d2 + d3*d3;
#pragma unroll
    for (int off = 16; off; off >>= 1) sq += __shfl_xor_sync(0xffffffffu, sq, off);
    float rstd = rsqrtf(sq * (1.0f/128.0f) + 1e-5f);
    int ri = r0 + row;
    out[(size_t)ri*FB + lane     ] = d0*rstd*lnw[lane     ] + lnb[lane     ];
    out[(size_t)ri*FB + lane + 32] = d1*rstd*lnw[lane + 32] + lnb[lane + 32];
    out[(size_t)ri*FB + lane + 64] = d2*rstd*lnw[lane + 64] + lnb[lane + 64];
    out[(size_t)ri*FB + lane + 96] = d3*rstd*lnw[lane + 96] + lnb[lane + 96];
}

extern "C" void kernel_launch(void* const* d_in, const int* in_sizes, int n_in,
                              void* d_out, int out_size) {
    const float* R    = (const float*)d_in[0];
    const float* tv   = (const float*)d_in[1];
    const float* pCB  = (const float*)d_in[2];
    const float* x    = (const float*)d_in[3];
    const float* z    = (const float*)d_in[4];
    const void*  mask = d_in[5];
    const float* Wq   = (const float*)d_in[6];
    const float* Wk   = (const float*)d_in[7];
    const float* Wv   = (const float*)d_in[8];
    const float* Wpb  = (const float*)d_in[9];
    const float* gr   = (const float*)d_in[10];
    const float* Wout = (const float*)d_in[11];
    const float* bo   = (const float*)d_in[12];
    const float* lnw  = (const float*)d_in[13];
    const float* lnb  = (const float*)d_in[14];
    float* out = (float*)d_out;

    decode_mask_kernel<<<1, NL>>>(mask);
    qkv_kernel<<<NL/8, 576>>>(x, Wq, Wk, Wv);
    attn_kernel<<<NL, 256, (2*TJ*CB + 2*LB)*sizeof(float)>>>(R, tv, pCB, z, Wpb, gr);
    out_kernel<<<NL/ORPB, 256>>>(x, Wout, bo, lnw, lnb, out);
}

// round 7
// speedup vs baseline: 1.1676x; 1.1007x over previous
#include <cuda_runtime.h>
#include <math.h>

#define NB 2
#define LB 512
#define FB 128
#define CB 64
#define HB 12
#define DB 16
#define NL (NB*LB)               // 1024
#define QKV (HB*DB)              // 192
#define FEAT (HB*CB + HB*DB + HB*7)  // 1044
#define FEATP 1088               // padded K for GEMM (17 * 64)
#define TJ 64
#define NTILES (LB/TJ)           // 8
#define INFV 100000.0f
#define SQ29V 0.47140452079103173f
#define SCALEV 0.57735026918962576f

__device__ float g_q[NL*QKV];
__device__ float g_k[NL*QKV];
__device__ float g_vT[NB*QKV*LB];     // [n][hd][j]  (transposed v)
__device__ int   g_mask[NL];
__device__ float g_featsP[(size_t)NL*FEATP];   // zero-padded feature rows
__device__ float g_WoutP[(size_t)FB*FEATP];    // zero-padded Wout
__device__ float g_y[(size_t)NL*FB];           // pre-LN residual output

__device__ __forceinline__ void cp_async16(void* smem_dst, const void* gmem_src) {
    unsigned s = (unsigned)__cvta_generic_to_shared(smem_dst);
    asm volatile("cp.async.cg.shared.global [%0], [%1], 16;\n" :: "r"(s), "l"(gmem_src));
}
#define CP_COMMIT() asm volatile("cp.async.commit_group;\n")
#define CP_WAIT1()  asm volatile("cp.async.wait_group 1;\n")
#define CP_WAIT0()  asm volatile("cp.async.wait_group 0;\n")

// ---------------------------------------------------------------------------
// Kernel A: decode mask input of ambiguous serialized dtype (bool/int32/fp32).
// ---------------------------------------------------------------------------
__global__ void decode_mask_kernel(const void* __restrict__ mraw) {
    __shared__ int cnt[4];
    int t = threadIdx.x;
    if (t < 4) cnt[t] = 0;
    __syncthreads();
    const unsigned char* b = (const unsigned char*)mraw;
    unsigned char v = b[t];
    if (v) atomicAdd(&cnt[t & 3], 1);
    __syncthreads();
    int m;
    if (cnt[1] | cnt[2] | cnt[3]) {
        if (cnt[0]) m = (b[t] != 0);                          // bool bytes
        else        m = (((const float*)mraw)[t] != 0.0f);    // float32
    } else {
        if (cnt[0]) m = (((const int*)mraw)[t] != 0);         // int32
        else        m = 0;
    }
    g_mask[t] = m;
}

// ---------------------------------------------------------------------------
// Kernel A2: copy Wout into zero-padded g_WoutP.
// ---------------------------------------------------------------------------
__global__ void prepw_kernel(const float* __restrict__ Wout) {
    int f = blockIdx.x;
    for (int k = threadIdx.x; k < FEATP; k += 256)
        g_WoutP[(size_t)f*FEATP + k] = (k < FEAT) ? Wout[(size_t)f*FEAT + k] : 0.f;
}

// ---------------------------------------------------------------------------
// Kernel B: QKV projection. 8 rows/block; 576 threads = 3 mats x 192 outputs.
// v is written TRANSPOSED: g_vT[n][hd][j].
// ---------------------------------------------------------------------------
__global__ __launch_bounds__(576) void qkv_kernel(
    const float* __restrict__ x,
    const float* __restrict__ Wq,
    const float* __restrict__ Wk,
    const float* __restrict__ Wv)
{
    __shared__ float xs[8][FB];
    int t = threadIdx.x;
    int r0 = blockIdx.x * 8;
    for (int idx = t; idx < 8*FB; idx += 576)
        xs[idx >> 7][idx & 127] = x[(size_t)r0*FB + idx];
    __syncthreads();

    int which = t / QKV;        // 0:q 1:k 2:v
    int o = t - which*QKV;
    const float* W = (which == 0) ? Wq : (which == 1) ? Wk : Wv;
    const float4* W4 = (const float4*)(W + (size_t)o*FB);

    float acc[8];
#pragma unroll
    for (int r = 0; r < 8; r++) acc[r] = 0.f;

    for (int kk = 0; kk < FB/4; kk++) {
        float4 w = __ldg(&W4[kk]);
#pragma unroll
        for (int r = 0; r < 8; r++) {
            float4 xv = *(const float4*)&xs[r][kk*4];
            acc[r] += w.x*xv.x + w.y*xv.y + w.z*xv.z + w.w*xv.w;
        }
    }
    if (which == 2) {
        int n = r0 >> 9, jb = r0 & (LB-1);
        float* vp = g_vT + ((size_t)n*QKV + o)*LB + jb;
#pragma unroll
        for (int r = 0; r < 8; r++) vp[r] = acc[r];
    } else {
        float* outp = (which == 0) ? g_q : g_k;
#pragma unroll
        for (int r = 0; r < 8; r++)
            outp[(size_t)(r0 + r)*QKV + o] = acc[r];
    }
}

// ---------------------------------------------------------------------------
// Kernel C: fused flash attention over j for one (n,i) per block.
// z read once (cp.async double buffered). Stage-6 accumulators live in
// registers across all tiles. Total smem kept under the 48KB default limit.
// ---------------------------------------------------------------------------
__global__ __launch_bounds__(256) void attn_kernel(
    const float* __restrict__ R,
    const float* __restrict__ tvec,
    const float* __restrict__ pCB,
    const float* __restrict__ z,
    const float* __restrict__ Wpb,
    const float* __restrict__ gamma_raw)
{
    const int ni = blockIdx.x;
    const int n = ni / LB;
    const int t = threadIdx.x;

    extern __shared__ float sm[];
    float* zsb[2] = { sm, sm + TJ*CB };        // 2 x 4096
    float* d2s  = sm + 2*TJ*CB;                // 512
    float* mfac = d2s + LB;                    // 512
    // final-reduction partial buffer reuses the zs region: part[4][768]

    __shared__ float qs[QKV];
    __shared__ float WpbT[CB*HB];
    __shared__ __align__(16) float lg[TJ*HB];  // [j][h], stride 12, rows 16B-aligned
    __shared__ float pmax[HB*16];
    __shared__ float mhead[HB], sheads[HB], scaleF[HB], invH[HB], coefH[HB];
    __shared__ float accPs[36];
    __shared__ float pci[3];
    __shared__ int rowValid;

    const size_t zrow = (size_t)ni * LB * CB;

    // prefetch z tile 0
    {
        const float4* zg = (const float4*)(z + zrow);
        float4* dst = (float4*)zsb[0];
#pragma unroll
        for (int r = 0; r < 4; r++) cp_async16(dst + t + 256*r, zg + t + 256*r);
        CP_COMMIT();
    }

    // ---- init A ----
    if (t < QKV) qs[t] = g_q[(size_t)ni*QKV + t];
    for (int o = t; o < HB*CB; o += 256) {
        int h = o / CB, c = o - h*CB;
        WpbT[c*HB + h] = Wpb[o];
    }
    if (t < HB) {
        float g = gamma_raw[t];
        float sp = log1pf(__expf(g));             // softplus
        coefH[t] = -sp * SQ29V * 0.5f;
        mhead[t] = -INFINITY;
    }
    if (t < 3) pci[t] = pCB[(size_t)ni*3 + t];
    if (t == 0) rowValid = g_mask[ni];
    __syncthreads();

    // ---- init B: per-j d2 / mask for ALL 512 j ----
    for (int j = t; j < LB; j += 256) {
        const float* pj = pCB + (size_t)(n*LB + j)*3;
        float dx = pj[0] - pci[0], dy = pj[1] - pci[1], dz = pj[2] - pci[2];
        d2s[j] = dx*dx + dy*dy + dz*dz;
        mfac[j] = (rowValid && g_mask[n*LB + j]) ? 0.f : -INFV;
    }
    // (ordered by the first in-loop __syncthreads)

    // persistent per-thread accumulators
    float2 az[12];                 // group A (t<128): accZ partial [h][2c]
#pragma unroll
    for (int h = 0; h < 12; h++) az[h] = make_float2(0.f, 0.f);
    float bv0 = 0.f, bv1 = 0.f, bv2 = 0.f;   // group B (128<=t<192): 3 vT rows
    float c0 = 0.f, c1 = 0.f;                // group C (192<=t<256)

    const int cq   = t & 31;       // group A: c-pair index (2 c's)
    const int jsub = (t >> 5) & 3; // group A: j subset (16 j)
    const int tb   = t - 128;      // group B index 0..63
    const int tc   = t - 192;      // group C index 0..63

    for (int jt = 0; jt < NTILES; jt++) {
        const int j0 = jt * TJ;
        const int buf = jt & 1;

        if (jt < NTILES-1) {
            const float4* zg = (const float4*)(z + zrow + (size_t)(j0+TJ)*CB);
            float4* dst = (float4*)zsb[buf^1];
#pragma unroll
            for (int r = 0; r < 4; r++) cp_async16(dst + t + 256*r, zg + t + 256*r);
            CP_COMMIT();
            CP_WAIT1();
        } else {
            CP_WAIT0();
        }
        __syncthreads();

        const float* zs = zsb[buf];

        // stage 3: logits (node + z·Wpb + beta·d2)*SCALE + mask -> lg[j][h]
#pragma unroll
        for (int r = 0; r < 3; r++) {
            int item = t + 256*r;                 // item == j*HB + h
            int j = item / HB, h = item - j*HB;
            const float4* kp = (const float4*)(g_k + (size_t)(n*LB + j0 + j)*QKV + h*DB);
            const float4* qp = (const float4*)(qs + h*DB);
            float acc = 0.f;
#pragma unroll
            for (int m4 = 0; m4 < 4; m4++) {
                float4 kv = __ldg(&kp[m4]);
                float4 qv = qp[m4];
                acc += kv.x*qv.x + kv.y*qv.y + kv.z*qv.z + kv.w*qv.w;
            }
            const float4* z4 = (const float4*)(zs + j*CB);
            const float* wc = WpbT + h;
#pragma unroll
            for (int c4 = 0; c4 < CB/4; c4++) {
                float4 zv = z4[c4];
                acc += zv.x*wc[(c4*4+0)*HB] + zv.y*wc[(c4*4+1)*HB]
                     + zv.z*wc[(c4*4+2)*HB] + zv.w*wc[(c4*4+3)*HB];
            }
            acc += coefH[h] * d2s[j0 + j];
            lg[item] = acc * SCALEV + mfac[j0 + j];
        }
        __syncthreads();

        // stage 4a: partial per-head max (192 threads, 4 j each)
        if (t < 192) {
            int h = t % HB, seg = t / HB;
            float tm = lg[(seg*4+0)*HB + h];
            tm = fmaxf(tm, lg[(seg*4+1)*HB + h]);
            tm = fmaxf(tm, lg[(seg*4+2)*HB + h]);
            tm = fmaxf(tm, lg[(seg*4+3)*HB + h]);
            pmax[h*16 + seg] = tm;
        }
        __syncthreads();
        // stage 4b
        if (t < HB) {
            float tm = pmax[t*16];
#pragma unroll
            for (int s = 1; s < 16; s++) tm = fmaxf(tm, pmax[t*16 + s]);
            float nm = fmaxf(mhead[t], tm);
            scaleF[t] = __expf(mhead[t] - nm);
            mhead[t] = nm;
        }
        __syncthreads();

        // stage 5: p = exp(lg - m)
#pragma unroll
        for (int r = 0; r < 3; r++) {
            int item = t + 256*r;
            int h = item % HB;
            lg[item] = __expf(lg[item] - mhead[h]);
        }
        __syncthreads();

        // stage 6: register accumulation (each group rescales its regs first)
        if (t < 128) {
            // accZ partial: 2 c's (cq), 16 j (jsub)
#pragma unroll
            for (int h = 0; h < 12; h++) {
                float s = scaleF[h];
                az[h].x *= s; az[h].y *= s;
            }
            const float2* z2 = (const float2*)zs;
#pragma unroll 4
            for (int jj = 0; jj < 16; jj++) {
                int j = jsub*16 + jj;
                float2 zv = z2[j*32 + cq];
                const float4* p4 = (const float4*)(lg + j*12);
                float4 pa = p4[0], pb = p4[1], pc = p4[2];
                az[0].x += pa.x*zv.x; az[0].y += pa.x*zv.y;
                az[1].x += pa.y*zv.x; az[1].y += pa.y*zv.y;
                az[2].x += pa.z*zv.x; az[2].y += pa.z*zv.y;
                az[3].x += pa.w*zv.x; az[3].y += pa.w*zv.y;
                az[4].x += pb.x*zv.x; az[4].y += pb.x*zv.y;
                az[5].x += pb.y*zv.x; az[5].y += pb.y*zv.y;
                az[6].x += pb.z*zv.x; az[6].y += pb.z*zv.y;
                az[7].x += pb.w*zv.x; az[7].y += pb.w*zv.y;
                az[8].x += pc.x*zv.x; az[8].y += pc.x*zv.y;
                az[9].x += pc.y*zv.x; az[9].y += pc.y*zv.y;
                az[10].x += pc.z*zv.x; az[10].y += pc.z*zv.y;
                az[11].x += pc.w*zv.x; az[11].y += pc.w*zv.y;
            }
        } else if (t < 192) {
            // p·v : 3 contiguous vT rows (tb, tb+64, tb+128)
            int h0 = tb >> 4, h1 = (tb+64) >> 4, h2 = (tb+128) >> 4;
            bv0 *= scaleF[h0]; bv1 *= scaleF[h1]; bv2 *= scaleF[h2];
            const float* vbase = g_vT + (size_t)n*QKV*LB + j0;
            const float4* v0 = (const float4*)(vbase + (size_t)(tb      )*LB);
            const float4* v1 = (const float4*)(vbase + (size_t)(tb +  64)*LB);
            const float4* v2 = (const float4*)(vbase + (size_t)(tb + 128)*LB);
#pragma unroll 4
            for (int q4 = 0; q4 < TJ/4; q4++) {
                float4 x0 = __ldg(v0+q4), x1 = __ldg(v1+q4), x2 = __ldg(v2+q4);
                int j = q4*4;
                bv0 += x0.x*lg[(j+0)*12+h0] + x0.y*lg[(j+1)*12+h0]
                     + x0.z*lg[(j+2)*12+h0] + x0.w*lg[(j+3)*12+h0];
                bv1 += x1.x*lg[(j+0)*12+h1] + x1.y*lg[(j+1)*12+h1]
                     + x1.z*lg[(j+2)*12+h1] + x1.w*lg[(j+3)*12+h1];
                bv2 += x2.x*lg[(j+0)*12+h2] + x2.y*lg[(j+1)*12+h2]
                     + x2.z*lg[(j+2)*12+h2] + x2.w*lg[(j+3)*12+h2];
            }
        } else {
            // tc<36 -> accP(h=tc/3, cc=tc%3); 36..47 -> sum p
            if (tc < 36) {
                int h = tc / 3, cc = tc - h*3;
                c0 *= scaleF[h];
                const float* pb = pCB + (size_t)(n*LB + j0)*3 + cc;
                float a = 0.f;
                for (int j = 0; j < TJ; j++)
                    a += lg[j*12 + h] * __ldg(pb + j*3);
                c0 += a;
            } else if (tc < 48) {
                int h = tc - 36;
                c1 *= scaleF[h];
                float s = 0.f;
                for (int j = 0; j < TJ; j++) s += lg[j*12 + h];
                c1 += s;
            }
        }
        __syncthreads();
    }

    // ---- finalize ----
    float* part = sm;   // reuse z buffers: part[4][768]
    if (t < 128) {
#pragma unroll
        for (int h = 0; h < 12; h++)
            ((float2*)(part + jsub*768 + h*64))[cq] = az[h];
    } else if (t >= 192) {
        if (tc < 36) accPs[tc] = c0;
        else if (tc < 48) sheads[tc - 36] = c1;
    }
    __syncthreads();
    if (t < HB) invH[t] = rowValid ? (1.0f / sheads[t]) : 0.f;
    __syncthreads();

    float* fo = g_featsP + (size_t)ni*FEATP;
    // feat_p2n: reduce 4 partials
    for (int o = t; o < HB*CB; o += 256) {
        float v = part[o] + part[768 + o] + part[1536 + o] + part[2304 + o];
        fo[o] = v * invH[o >> 6];
    }
    // feat_node
    if (t >= 128 && t < 192) {
        fo[HB*CB + tb      ] = bv0 * invH[tb >> 4];
        fo[HB*CB + tb +  64] = bv1 * invH[(tb+64) >> 4];
        fo[HB*CB + tb + 128] = bv2 * invH[(tb+128) >> 4];
    }
    // spatial features
    if (t < HB) {
        int h = t;
        float inv = invH[h];
        float a0 = accPs[h*3+0]*inv - tvec[(size_t)ni*3+0];
        float a1 = accPs[h*3+1]*inv - tvec[(size_t)ni*3+1];
        float a2 = accPs[h*3+2]*inv - tvec[(size_t)ni*3+2];
        const float* Rp = R + (size_t)ni*9;          // local = R^T (a - t)
        float l0 = Rp[0]*a0 + Rp[3]*a1 + Rp[6]*a2;
        float l1 = Rp[1]*a0 + Rp[4]*a1 + Rp[7]*a2;
        float l2 = Rp[2]*a0 + Rp[5]*a1 + Rp[8]*a2;
        float dist = sqrtf(l0*l0 + l1*l1 + l2*l2);
        float idn = 1.0f / (dist + 1e-4f);
        const int b0 = HB*CB + HB*DB;                // 960
        fo[b0 + h*3 + 0] = l0;
        fo[b0 + h*3 + 1] = l1;
        fo[b0 + h*3 + 2] = l2;
        fo[b0 + 36 + h]  = dist;
        fo[b0 + 48 + h*3 + 0] = l0*idn;
        fo[b0 + 48 + h*3 + 1] = l1*idn;
        fo[b0 + 48 + h*3 + 2] = l2*idn;
    }
    // zero pad
    if (t < FEATP - FEAT) fo[FEAT + t] = 0.f;
}

// ---------------------------------------------------------------------------
// Kernel D1: output projection as tiled GEMM. 32x32 tile per block.
// grid = 32 row-blocks x 4 f-blocks = 128. K double-buffered via cp.async.
// ---------------------------------------------------------------------------
#define KT 64
#define NKT (FEATP/KT)      // 17
#define TS 68               // padded smem row stride (floats)

__global__ __launch_bounds__(256) void proj_kernel(
    const float* __restrict__ x,
    const float* __restrict__ bout)
{
    __shared__ float fsT[2][32*TS];
    __shared__ float wsT[2][32*TS];
    int t = threadIdx.x;
    int mb = blockIdx.x & 31, fb = blockIdx.x >> 5;
    int r0 = mb*32, f0 = fb*32;

    const float* fbase = g_featsP + (size_t)r0*FEATP;
    const float* wbase = g_WoutP  + (size_t)f0*FEATP;

    {
#pragma unroll
        for (int rep = 0; rep < 2; rep++) {
            int idx = t + rep*256;
            int row = idx >> 4, col = idx & 15;
            cp_async16(&fsT[0][row*TS + col*4], fbase + (size_t)row*FEATP + col*4);
            cp_async16(&wsT[0][row*TS + col*4], wbase + (size_t)row*FEATP + col*4);
        }
        CP_COMMIT();
    }

    int tr = t >> 4, tf = t & 15;
    float a00 = 0.f, a01 = 0.f, a10 = 0.f, a11 = 0.f;

    for (int kt = 0; kt < NKT; kt++) {
        int buf = kt & 1;
        if (kt < NKT-1) {
#pragma unroll
            for (int rep = 0; rep < 2; rep++) {
                int idx = t + rep*256;
                int row = idx >> 4, col = idx & 15;
                cp_async16(&fsT[buf^1][row*TS + col*4],
                           fbase + (size_t)row*FEATP + (kt+1)*KT + col*4);
                cp_async16(&wsT[buf^1][row*TS + col*4],
                           wbase + (size_t)row*FEATP + (kt+1)*KT + col*4);
            }
            CP_COMMIT();
            CP_WAIT1();
        } else {
            CP_WAIT0();
        }
        __syncthreads();

        const float4* fr0 = (const float4*)&fsT[buf][(tr*2  )*TS];
        const float4* fr1 = (const float4*)&fsT[buf][(tr*2+1)*TS];
        const float4* wr0 = (const float4*)&wsT[buf][(tf*2  )*TS];
        const float4* wr1 = (const float4*)&wsT[buf][(tf*2+1)*TS];
#pragma unroll
        for (int k4 = 0; k4 < KT/4; k4++) {
            float4 xa = fr0[k4], xb = fr1[k4];
            float4 wa = wr0[k4], wb = wr1[k4];
            a00 += xa.x*wa.x + xa.y*wa.y + xa.z*wa.z + xa.w*wa.w;
            a01 += xa.x*wb.x + xa.y*wb.y + xa.z*wb.z + xa.w*wb.w;
            a10 += xb.x*wa.x + xb.y*wa.y + xb.z*wa.z + xb.w*wa.w;
            a11 += xb.x*wb.x + xb.y*wb.y + xb.z*wb.z + xb.w*wb.w;
        }
        __syncthreads();
    }

    int ri0 = r0 + tr*2, ri1 = ri0 + 1;
    int fA = f0 + tf*2, fB2 = fA + 1;
    float bA = __ldg(&bout[fA]), bB = __ldg(&bout[fB2]);
    int m0 = g_mask[ri0], m1 = g_mask[ri1];
    g_y[(size_t)ri0*FB + fA ] = x[(size_t)ri0*FB + fA ] + (m0 ? (a00 + bA) : 0.f);
    g_y[(size_t)ri0*FB + fB2] = x[(size_t)ri0*FB + fB2] + (m0 ? (a01 + bB) : 0.f);
    g_y[(size_t)ri1*FB + fA ] = x[(size_t)ri1*FB + fA ] + (m1 ? (a10 + bA) : 0.f);
    g_y[(size_t)ri1*FB + fB2] = x[(size_t)ri1*FB + fB2] + (m1 ? (a11 + bB) : 0.f);
}

// ---------------------------------------------------------------------------
// Kernel D2: LayerNorm over g_y. One warp per row.
// ---------------------------------------------------------------------------
__global__ __launch_bounds__(256) void ln_kernel(
    const float* __restrict__ lnw,
    const float* __restrict__ lnb,
    float* __restrict__ out)
{
    int t = threadIdx.x;
    int wid = t >> 5, lane = t & 31;
    int ri = blockIdx.x * 8 + wid;
    const float* yr = g_y + (size_t)ri*FB;
    float v0 = yr[lane], v1 = yr[lane+32], v2 = yr[lane+64], v3 = yr[lane+96];
    float s = v0 + v1 + v2 + v3;
#pragma unroll
    for (int off = 16; off; off >>= 1) s += __shfl_xor_sync(0xffffffffu, s, off);
    float mu = s * (1.0f/128.0f);
    float d0 = v0-mu, d1 = v1-mu, d2 = v2-mu, d3 = v3-mu;
    float sq = d0*d0 + d1*d1 + d2*d2 + d3*d3;
#pragma unroll
    for (int off = 16; off; off >>= 1) sq += __shfl_xor_sync(0xffffffffu, sq, off);
    float rstd = rsqrtf(sq * (1.0f/128.0f) + 1e-5f);
    out[(size_t)ri*FB + lane     ] = d0*rstd*lnw[lane     ] + lnb[lane     ];
    out[(size_t)ri*FB + lane + 32] = d1*rstd*lnw[lane + 32] + lnb[lane + 32];
    out[(size_t)ri*FB + lane + 64] = d2*rstd*lnw[lane + 64] + lnb[lane + 64];
    out[(size_t)ri*FB + lane + 96] = d3*rstd*lnw[lane + 96] + lnb[lane + 96];
}

extern "C" void kernel_launch(void* const* d_in, const int* in_sizes, int n_in,
                              void* d_out, int out_size) {
    const float* R    = (const float*)d_in[0];
    const float* tv   = (const float*)d_in[1];
    const float* pCB  = (const float*)d_in[2];
    const float* x    = (const float*)d_in[3];
    const float* z    = (const float*)d_in[4];
    const void*  mask = d_in[5];
    const float* Wq   = (const float*)d_in[6];
    const float* Wk   = (const float*)d_in[7];
    const float* Wv   = (const float*)d_in[8];
    const float* Wpb  = (const float*)d_in[9];
    const float* gr   = (const float*)d_in[10];
    const float* Wout = (const float*)d_in[11];
    const float* bo   = (const float*)d_in[12];
    const float* lnw  = (const float*)d_in[13];
    const float* lnb  = (const float*)d_in[14];
    float* out = (float*)d_out;

    decode_mask_kernel<<<1, NL>>>(mask);
    prepw_kernel<<<FB, 256>>>(Wout);
    qkv_kernel<<<NL/8, 576>>>(x, Wq, Wk, Wv);
    size_t attn_smem = (2*TJ*CB + 2*LB)*sizeof(float);   // 36864 B
    attn_kernel<<<NL, 256, attn_smem>>>(R, tv, pCB, z, Wpb, gr);
    proj_kernel<<<128, 256>>>(x, bo);
    ln_kernel<<<NL/8, 256>>>(lnw, lnb, out);
}

// round 8
// speedup vs baseline: 2.5602x; 2.1927x over previous
#include <cuda_runtime.h>
#include <math.h>

#define NB 2
#define LB 512
#define FB 128
#define CB 64
#define HB 12
#define DB 16
#define NL (NB*LB)               // 1024
#define NH (NB*HB)               // 24
#define FEAT 1044
#define FEATP 1088
#define INFV 100000.0f
#define SQ29V 0.47140452079103173f
#define SCALEV 0.57735026918962576f

__device__ float g_qh[(size_t)NH*LB*DB];     // [n][h][i][d]
__device__ float g_kh[(size_t)NH*LB*DB];
__device__ float g_vh[(size_t)NH*LB*DB];
__device__ int   g_mask[NL];
__device__ float g_alpha[(size_t)NH*LB*LB];    // node logits -> alpha [n][h][i][j]
__device__ float g_alphaT3[(size_t)NL*LB*HB];  // alpha [n][i][j][h] packed 12
__device__ float g_accP[(size_t)NH*LB*3];
__device__ float g_featsP[(size_t)NL*FEATP];
__device__ float g_WoutP[(size_t)FB*FEATP];
__device__ float g_y[(size_t)NL*FB];

__device__ __forceinline__ void cp_async16(void* smem_dst, const void* gmem_src) {
    unsigned s = (unsigned)__cvta_generic_to_shared(smem_dst);
    asm volatile("cp.async.cg.shared.global [%0], [%1], 16;\n" :: "r"(s), "l"(gmem_src));
}
#define CP_COMMIT() asm volatile("cp.async.commit_group;\n")
#define CP_WAIT1()  asm volatile("cp.async.wait_group 1;\n")
#define CP_WAIT0()  asm volatile("cp.async.wait_group 0;\n")

// ---------------------------------------------------------------------------
// A: decode mask of ambiguous serialized dtype (bool/int32/fp32).
// ---------------------------------------------------------------------------
__global__ void decode_mask_kernel(const void* __restrict__ mraw) {
    __shared__ int cnt[4];
    int t = threadIdx.x;
    if (t < 4) cnt[t] = 0;
    __syncthreads();
    const unsigned char* b = (const unsigned char*)mraw;
    unsigned char v = b[t];
    if (v) atomicAdd(&cnt[t & 3], 1);
    __syncthreads();
    int m;
    if (cnt[1] | cnt[2] | cnt[3]) {
        if (cnt[0]) m = (b[t] != 0);
        else        m = (((const float*)mraw)[t] != 0.0f);
    } else {
        if (cnt[0]) m = (((const int*)mraw)[t] != 0);
        else        m = 0;
    }
    g_mask[t] = m;
}

// ---------------------------------------------------------------------------
// A2: zero-padded Wout copy.
// ---------------------------------------------------------------------------
__global__ void prepw_kernel(const float* __restrict__ Wout) {
    int f = blockIdx.x;
    for (int k = threadIdx.x; k < FEATP; k += 256)
        g_WoutP[(size_t)f*FEATP + k] = (k < FEAT) ? Wout[(size_t)f*FEAT + k] : 0.f;
}

// ---------------------------------------------------------------------------
// B: QKV projection -> per-head layouts [n][h][idx][d].
// ---------------------------------------------------------------------------
__global__ __launch_bounds__(576) void qkv_kernel(
    const float* __restrict__ x,
    const float* __restrict__ Wq,
    const float* __restrict__ Wk,
    const float* __restrict__ Wv)
{
    __shared__ float xs[8][FB];
    int t = threadIdx.x;
    int r0 = blockIdx.x * 8;
    for (int idx = t; idx < 8*FB; idx += 576)
        xs[idx >> 7][idx & 127] = x[(size_t)r0*FB + idx];
    __syncthreads();

    int which = t / 192;
    int o = t - which*192;
    const float* W = (which == 0) ? Wq : (which == 1) ? Wk : Wv;
    float* outp    = (which == 0) ? g_qh : (which == 1) ? g_kh : g_vh;
    const float4* W4 = (const float4*)(W + (size_t)o*FB);

    float acc[8];
#pragma unroll
    for (int r = 0; r < 8; r++) acc[r] = 0.f;
    for (int kk = 0; kk < FB/4; kk++) {
        float4 w = __ldg(&W4[kk]);
#pragma unroll
        for (int r = 0; r < 8; r++) {
            float4 xv = *(const float4*)&xs[r][kk*4];
            acc[r] += w.x*xv.x + w.y*xv.y + w.z*xv.z + w.w*xv.w;
        }
    }
    int h = o >> 4, d = o & 15;
#pragma unroll
    for (int r = 0; r < 8; r++) {
        int row = r0 + r;
        int n = row >> 9, i = row & 511;
        outp[((size_t)(n*HB + h)*LB + i)*DB + d] = acc[r];
    }
}

// ---------------------------------------------------------------------------
// C1: node logits GEMM. Per (n,h): [512x16]x[16x512] -> g_alpha (raw dots).
// grid 24*64, block 256, 64x64 tiles, 4x4 per thread.
// ---------------------------------------------------------------------------
__global__ __launch_bounds__(256) void qk_kernel()
{
    __shared__ float Qs[64*17], Ks[64*17];
    int b = blockIdx.x;
    int nh = b >> 6, tile = b & 63;
    int i0 = (tile >> 3)*64, j0 = (tile & 7)*64;
    int t = threadIdx.x;
    {
        int r = t >> 2, c4 = t & 3;
        float4 qv = *(const float4*)(g_qh + ((size_t)nh*LB + i0 + r)*DB + c4*4);
        Qs[r*17+c4*4+0]=qv.x; Qs[r*17+c4*4+1]=qv.y; Qs[r*17+c4*4+2]=qv.z; Qs[r*17+c4*4+3]=qv.w;
        float4 kv = *(const float4*)(g_kh + ((size_t)nh*LB + j0 + r)*DB + c4*4);
        Ks[r*17+c4*4+0]=kv.x; Ks[r*17+c4*4+1]=kv.y; Ks[r*17+c4*4+2]=kv.z; Ks[r*17+c4*4+3]=kv.w;
    }
    __syncthreads();
    int ti = t >> 4, tj = t & 15;
    float acc[4][4];
#pragma unroll
    for (int a = 0; a < 4; a++)
#pragma unroll
        for (int bb = 0; bb < 4; bb++) acc[a][bb] = 0.f;
    const float* Qb = Qs + (ti*4)*17;
    const float* Kb = Ks + (tj*4)*17;
#pragma unroll
    for (int d = 0; d < 16; d++) {
        float q0=Qb[d], q1=Qb[17+d], q2=Qb[34+d], q3=Qb[51+d];
        float k0=Kb[d], k1=Kb[17+d], k2=Kb[34+d], k3=Kb[51+d];
        acc[0][0]+=q0*k0; acc[0][1]+=q0*k1; acc[0][2]+=q0*k2; acc[0][3]+=q0*k3;
        acc[1][0]+=q1*k0; acc[1][1]+=q1*k1; acc[1][2]+=q1*k2; acc[1][3]+=q1*k3;
        acc[2][0]+=q2*k0; acc[2][1]+=q2*k1; acc[2][2]+=q2*k2; acc[2][3]+=q2*k3;
        acc[3][0]+=q3*k0; acc[3][1]+=q3*k1; acc[3][2]+=q3*k2; acc[3][3]+=q3*k3;
    }
    float* outb = g_alpha + ((size_t)nh*LB + i0 + ti*4)*LB + j0 + tj*4;
#pragma unroll
    for (int k = 0; k < 4; k++) {
        float4 o = make_float4(acc[k][0], acc[k][1], acc[k][2], acc[k][3]);
        *(float4*)(outb + (size_t)k*LB) = o;
    }
}

// ---------------------------------------------------------------------------
// C2: pair bias + beta + mask + softmax per (n,i). Streams z (read #1).
// In-place RMW on g_alpha; also writes packed alphaT3 [j][12].
// ---------------------------------------------------------------------------
__global__ __launch_bounds__(256) void pair_softmax_kernel(
    const float* __restrict__ pCB,
    const float* __restrict__ z,
    const float* __restrict__ Wpb,
    const float* __restrict__ gamma_raw)
{
    __shared__ float lgs[HB*LB];          // 24 KB
    __shared__ float4 WpbV[HB*16];        // 3 KB
    __shared__ float coefH[HB];
    __shared__ float pci[3];
    __shared__ int rowValid;

    int ni = blockIdx.x;
    int n = ni >> 9, i = ni & 511;
    int t = threadIdx.x;

    if (t < 192) WpbV[t] = __ldg(((const float4*)Wpb) + t);
    if (t < HB) {
        float g = gamma_raw[t];
        coefH[t] = -log1pf(__expf(g)) * SQ29V * 0.5f;
    }
    if (t < 3) pci[t] = pCB[(size_t)ni*3 + t];
    if (t == 0) rowValid = g_mask[ni];
    __syncthreads();

    const size_t zrow = (size_t)ni * LB * CB;
    const size_t lbase0 = (size_t)(n*HB)*LB*LB + (size_t)i*LB;

#pragma unroll
    for (int rep = 0; rep < 2; rep++) {
        int j = t + rep*256;
        const float* pj = pCB + (size_t)(n*LB + j)*3;
        float dx = pj[0]-pci[0], dy = pj[1]-pci[1], dz = pj[2]-pci[2];
        float d2 = dx*dx + dy*dy + dz*dz;
        float mf = (rowValid && g_mask[n*LB + j]) ? 0.f : -INFV;

        float acc[12];
#pragma unroll
        for (int h = 0; h < 12; h++)
            acc[h] = __ldg(g_alpha + lbase0 + (size_t)h*LB*LB + j) + coefH[h]*d2;

        const float4* z4 = (const float4*)(z + zrow + (size_t)j*CB);
#pragma unroll
        for (int c4 = 0; c4 < 16; c4++) {
            float4 zv = __ldg(z4 + c4);
#pragma unroll
            for (int h = 0; h < 12; h++) {
                float4 wv = WpbV[h*16 + c4];
                acc[h] += zv.x*wv.x + zv.y*wv.y + zv.z*wv.z + zv.w*wv.w;
            }
        }
#pragma unroll
        for (int h = 0; h < 12; h++)
            lgs[h*LB + j] = acc[h]*SCALEV + mf;
    }
    __syncthreads();

    // softmax per head row (Σα = 1 afterward, or 0 for invalid rows)
    int wid = t >> 5, lane = t & 31;
    for (int h = wid; h < HB; h += 8) {
        float* row = lgs + h*LB;
        float m = -INFINITY;
        for (int jj = lane; jj < LB; jj += 32) m = fmaxf(m, row[jj]);
#pragma unroll
        for (int off = 16; off; off >>= 1) m = fmaxf(m, __shfl_xor_sync(0xffffffffu, m, off));
        float s = 0.f;
        for (int jj = lane; jj < LB; jj += 32) {
            float e = __expf(row[jj] - m);
            s += e; row[jj] = e;
        }
#pragma unroll
        for (int off = 16; off; off >>= 1) s += __shfl_xor_sync(0xffffffffu, s, off);
        float inv = rowValid ? (1.f/s) : 0.f;
        float* ga = g_alpha + lbase0 + (size_t)h*LB*LB;
        for (int jj = lane; jj < LB; jj += 32) {
            float a = row[jj]*inv;
            row[jj] = a;
            ga[jj] = a;
        }
    }
    __syncthreads();

    // packed alphaT3 [j][12] (3 x float4 per j, contiguous)
    float* gt = g_alphaT3 + (size_t)ni*LB*HB;
#pragma unroll
    for (int rep = 0; rep < 2; rep++) {
        int j = t + rep*256;
        float4 o0 = make_float4(lgs[0*LB+j], lgs[1*LB+j], lgs[2*LB+j],  lgs[3*LB+j]);
        float4 o1 = make_float4(lgs[4*LB+j], lgs[5*LB+j], lgs[6*LB+j],  lgs[7*LB+j]);
        float4 o2 = make_float4(lgs[8*LB+j], lgs[9*LB+j], lgs[10*LB+j], lgs[11*LB+j]);
        float4* dst = (float4*)(gt + (size_t)j*HB);
        dst[0] = o0; dst[1] = o1; dst[2] = o2;
    }
}

// ---------------------------------------------------------------------------
// C3: feat_p2n = alpha · z per (n,i). Streams z (read #2) + alphaT3 tiles,
// both cp.async double-buffered. Register accumulators, no rescales.
// ---------------------------------------------------------------------------
#define TJ 64
__global__ __launch_bounds__(256) void p2n_kernel(const float* __restrict__ z)
{
    extern __shared__ float sm[];
    float* zsb[2] = { sm, sm + TJ*CB };               // 2 x 16 KB
    float* Asb[2] = { sm + 8192, sm + 8192 + 1024 };  // 2 x 4 KB [64][16]

    int ni = blockIdx.x, t = threadIdx.x;
    const size_t zrow = (size_t)ni * LB * CB;
    const float* at = g_alphaT3 + (size_t)ni*LB*HB;
    const int jA = t/3, pA = t - jA*3;   // alpha chunk decode (t<192)

    // prefetch tile 0
    {
        const float4* zg = (const float4*)(z + zrow);
        float4* dst = (float4*)zsb[0];
#pragma unroll
        for (int r = 0; r < 4; r++) cp_async16(dst + t + 256*r, zg + t + 256*r);
        if (t < 192) cp_async16(Asb[0] + jA*16 + pA*4, at + (size_t)t*4);
        CP_COMMIT();
    }

    float2 az[12];
#pragma unroll
    for (int h = 0; h < 12; h++) az[h] = make_float2(0.f, 0.f);
    const int cq = t & 31, jq = t >> 5;

    for (int jt = 0; jt < 8; jt++) {
        const int buf = jt & 1;
        if (jt < 7) {
            const float4* zg = (const float4*)(z + zrow + (size_t)(jt+1)*TJ*CB);
            float4* dst = (float4*)zsb[buf^1];
#pragma unroll
            for (int r = 0; r < 4; r++) cp_async16(dst + t + 256*r, zg + t + 256*r);
            if (t < 192) cp_async16(Asb[buf^1] + jA*16 + pA*4,
                                    at + (size_t)(jt+1)*768 + (size_t)t*4);
            CP_COMMIT();
            CP_WAIT1();
        } else {
            CP_WAIT0();
        }
        __syncthreads();

        const float* zs = zsb[buf];
        const float* As = Asb[buf];
#pragma unroll
        for (int jj = 0; jj < 8; jj++) {
            int j = jq*8 + jj;
            float2 zv = ((const float2*)zs)[j*32 + cq];
            const float4* p4 = (const float4*)(As + j*16);
            float4 pa = p4[0], pb = p4[1], pc = p4[2];
            az[0].x  += pa.x*zv.x; az[0].y  += pa.x*zv.y;
            az[1].x  += pa.y*zv.x; az[1].y  += pa.y*zv.y;
            az[2].x  += pa.z*zv.x; az[2].y  += pa.z*zv.y;
            az[3].x  += pa.w*zv.x; az[3].y  += pa.w*zv.y;
            az[4].x  += pb.x*zv.x; az[4].y  += pb.x*zv.y;
            az[5].x  += pb.y*zv.x; az[5].y  += pb.y*zv.y;
            az[6].x  += pb.z*zv.x; az[6].y  += pb.z*zv.y;
            az[7].x  += pb.w*zv.x; az[7].y  += pb.w*zv.y;
            az[8].x  += pc.x*zv.x; az[8].y  += pc.x*zv.y;
            az[9].x  += pc.y*zv.x; az[9].y  += pc.y*zv.y;
            az[10].x += pc.z*zv.x; az[10].y += pc.z*zv.y;
            az[11].x += pc.w*zv.x; az[11].y += pc.w*zv.y;
        }
        __syncthreads();
    }

    // reduce 8 jq-partials via smem (reuses z buffers)
    float* part = sm;   // [8][768]
#pragma unroll
    for (int h = 0; h < 12; h++)
        ((float2*)(part + jq*768 + h*64))[cq] = az[h];
    __syncthreads();

    float* fo = g_featsP + (size_t)ni*FEATP;
    for (int o = t; o < 768; o += 256) {
        float v = part[o] + part[768+o] + part[1536+o] + part[2304+o]
                + part[3072+o] + part[3840+o] + part[4608+o] + part[5376+o];
        fo[o] = v;
    }
    if (t < FEATP - FEAT) fo[FEAT + t] = 0.f;   // zero pad
}

// ---------------------------------------------------------------------------
// C4: feat_node (alpha·v) + accP (alpha·pCB) per (n,h) as tiled GEMM.
// grid 24*8 (i-tiles of 64), 320 threads = 64 i x 5 cols.
// ---------------------------------------------------------------------------
__global__ __launch_bounds__(320) void av_kernel(const float* __restrict__ pCB)
{
    __shared__ float As[64*65];   // transposed alpha tile [j][i]
    __shared__ float vs[64*16];
    __shared__ float ps[64*4];
    int b = blockIdx.x;
    int nh = b >> 3;
    int i0 = (b & 7)*64;
    int n = nh / HB, h = nh - n*HB;
    int t = threadIdx.x;
    int i_l = t & 63, col = t >> 6;          // col 0..4

    float a0 = 0.f, a1 = 0.f, a2 = 0.f, a3 = 0.f;

    for (int jt = 0; jt < 8; jt++) {
        int j0 = jt*64;
        __syncthreads();
        if (t < 256) {
            int r = t >> 2, c16 = t & 3;
            const float4* src = (const float4*)(g_alpha + ((size_t)nh*LB + i0 + r)*LB + j0 + c16*16);
#pragma unroll
            for (int q = 0; q < 4; q++) {
                float4 v = __ldg(src + q);
                int jj = c16*16 + q*4;
                As[(jj+0)*65 + r] = v.x;
                As[(jj+1)*65 + r] = v.y;
                As[(jj+2)*65 + r] = v.z;
                As[(jj+3)*65 + r] = v.w;
            }
            *(float4*)(vs + r*16 + c16*4) =
                *(const float4*)(g_vh + ((size_t)nh*LB + j0 + r)*DB + c16*4);
        } else {
            int tt = t - 256;   // 0..63
            const float* pb = pCB + (size_t)(n*LB + j0 + tt)*3;
            ps[tt*4+0] = pb[0]; ps[tt*4+1] = pb[1]; ps[tt*4+2] = pb[2]; ps[tt*4+3] = 0.f;
        }
        __syncthreads();

        if (col < 4) {
#pragma unroll 8
            for (int j = 0; j < 64; j++) {
                float a = As[j*65 + i_l];
                float4 vv = *(float4*)(vs + j*16 + col*4);
                a0 += a*vv.x; a1 += a*vv.y; a2 += a*vv.z; a3 += a*vv.w;
            }
        } else {
#pragma unroll 8
            for (int j = 0; j < 64; j++) {
                float a = As[j*65 + i_l];
                float4 pp = *(float4*)(ps + j*4);
                a0 += a*pp.x; a1 += a*pp.y; a2 += a*pp.z;
            }
        }
    }

    int i = i0 + i_l;
    if (col < 4) {
        float* fo = g_featsP + (size_t)(n*LB + i)*FEATP + 768 + h*16 + col*4;
        fo[0] = a0; fo[1] = a1; fo[2] = a2; fo[3] = a3;
    } else {
        float* ap = g_accP + ((size_t)nh*LB + i)*3;
        ap[0] = a0; ap[1] = a1; ap[2] = a2;
    }
}

// ---------------------------------------------------------------------------
// C5: spatial features. One thread per (n,i,h).
// ---------------------------------------------------------------------------
__global__ __launch_bounds__(256) void spatial_kernel(
    const float* __restrict__ R,
    const float* __restrict__ tvec)
{
    int gid = blockIdx.x*256 + threadIdx.x;   // 12288
    int ni = gid / HB, h = gid - ni*HB;
    int n = ni >> 9;
    const float* ap = g_accP + ((size_t)(n*HB + h)*LB + (ni & 511))*3;
    float a0 = ap[0] - tvec[(size_t)ni*3+0];
    float a1 = ap[1] - tvec[(size_t)ni*3+1];
    float a2 = ap[2] - tvec[(size_t)ni*3+2];
    const float* Rp = R + (size_t)ni*9;            // local = R^T (aggr - t)
    float l0 = Rp[0]*a0 + Rp[3]*a1 + Rp[6]*a2;
    float l1 = Rp[1]*a0 + Rp[4]*a1 + Rp[7]*a2;
    float l2 = Rp[2]*a0 + Rp[5]*a1 + Rp[8]*a2;
    float dist = sqrtf(l0*l0 + l1*l1 + l2*l2);
    float idn = 1.0f / (dist + 1e-4f);
    float* fo = g_featsP + (size_t)ni*FEATP + 960;
    fo[h*3+0] = l0; fo[h*3+1] = l1; fo[h*3+2] = l2;
    fo[36 + h] = dist;
    fo[48 + h*3+0] = l0*idn; fo[48 + h*3+1] = l1*idn; fo[48 + h*3+2] = l2*idn;
}

// ---------------------------------------------------------------------------
// D1: output projection tiled GEMM (unchanged from R7).
// ---------------------------------------------------------------------------
#define KT 64
#define NKT (FEATP/KT)
#define TS 68

__global__ __launch_bounds__(256) void proj_kernel(
    const float* __restrict__ x,
    const float* __restrict__ bout)
{
    __shared__ float fsT[2][32*TS];
    __shared__ float wsT[2][32*TS];
    int t = threadIdx.x;
    int mb = blockIdx.x & 31, fb = blockIdx.x >> 5;
    int r0 = mb*32, f0 = fb*32;

    const float* fbase = g_featsP + (size_t)r0*FEATP;
    const float* wbase = g_WoutP  + (size_t)f0*FEATP;
    {
#pragma unroll
        for (int rep = 0; rep < 2; rep++) {
            int idx = t + rep*256;
            int row = idx >> 4, col = idx & 15;
            cp_async16(&fsT[0][row*TS + col*4], fbase + (size_t)row*FEATP + col*4);
            cp_async16(&wsT[0][row*TS + col*4], wbase + (size_t)row*FEATP + col*4);
        }
        CP_COMMIT();
    }

    int tr = t >> 4, tf = t & 15;
    float a00 = 0.f, a01 = 0.f, a10 = 0.f, a11 = 0.f;
    for (int kt = 0; kt < NKT; kt++) {
        int buf = kt & 1;
        if (kt < NKT-1) {
#pragma unroll
            for (int rep = 0; rep < 2; rep++) {
                int idx = t + rep*256;
                int row = idx >> 4, col = idx & 15;
                cp_async16(&fsT[buf^1][row*TS + col*4],
                           fbase + (size_t)row*FEATP + (kt+1)*KT + col*4);
                cp_async16(&wsT[buf^1][row*TS + col*4],
                           wbase + (size_t)row*FEATP + (kt+1)*KT + col*4);
            }
            CP_COMMIT();
            CP_WAIT1();
        } else {
            CP_WAIT0();
        }
        __syncthreads();

        const float4* fr0 = (const float4*)&fsT[buf][(tr*2  )*TS];
        const float4* fr1 = (const float4*)&fsT[buf][(tr*2+1)*TS];
        const float4* wr0 = (const float4*)&wsT[buf][(tf*2  )*TS];
        const float4* wr1 = (const float4*)&wsT[buf][(tf*2+1)*TS];
#pragma unroll
        for (int k4 = 0; k4 < KT/4; k4++) {
            float4 xa = fr0[k4], xb = fr1[k4];
            float4 wa = wr0[k4], wb = wr1[k4];
            a00 += xa.x*wa.x + xa.y*wa.y + xa.z*wa.z + xa.w*wa.w;
            a01 += xa.x*wb.x + xa.y*wb.y + xa.z*wb.z + xa.w*wb.w;
            a10 += xb.x*wa.x + xb.y*wa.y + xb.z*wa.z + xb.w*wa.w;
            a11 += xb.x*wb.x + xb.y*wb.y + xb.z*wb.z + xb.w*wb.w;
        }
        __syncthreads();
    }

    int ri0 = r0 + tr*2, ri1 = ri0 + 1;
    int fA = f0 + tf*2, fB2 = fA + 1;
    float bA = __ldg(&bout[fA]), bB = __ldg(&bout[fB2]);
    int m0 = g_mask[ri0], m1 = g_mask[ri1];
    g_y[(size_t)ri0*FB + fA ] = x[(size_t)ri0*FB + fA ] + (m0 ? (a00 + bA) : 0.f);
    g_y[(size_t)ri0*FB + fB2] = x[(size_t)ri0*FB + fB2] + (m0 ? (a01 + bB) : 0.f);
    g_y[(size_t)ri1*FB + fA ] = x[(size_t)ri1*FB + fA ] + (m1 ? (a10 + bA) : 0.f);
    g_y[(size_t)ri1*FB + fB2] = x[(size_t)ri1*FB + fB2] + (m1 ? (a11 + bB) : 0.f);
}

// ---------------------------------------------------------------------------
// D2: LayerNorm.
// ---------------------------------------------------------------------------
__global__ __launch_bounds__(256) void ln_kernel(
    const float* __restrict__ lnw,
    const float* __restrict__ lnb,
    float* __restrict__ out)
{
    int t = threadIdx.x;
    int wid = t >> 5, lane = t & 31;
    int ri = blockIdx.x * 8 + wid;
    const float* yr = g_y + (size_t)ri*FB;
    float v0 = yr[lane], v1 = yr[lane+32], v2 = yr[lane+64], v3 = yr[lane+96];
    float s = v0 + v1 + v2 + v3;
#pragma unroll
    for (int off = 16; off; off >>= 1) s += __shfl_xor_sync(0xffffffffu, s, off);
    float mu = s * (1.0f/128.0f);
    float d0 = v0-mu, d1 = v1-mu, d2 = v2-mu, d3 = v3-mu;
    float sq = d0*d0 + d1*d1 + d2*d2 + d3*d3;
#pragma unroll
    for (int off = 16; off; off >>= 1) sq += __shfl_xor_sync(0xffffffffu, sq, off);
    float rstd = rsqrtf(sq * (1.0f/128.0f) + 1e-5f);
    out[(size_t)ri*FB + lane     ] = d0*rstd*lnw[lane     ] + lnb[lane     ];
    out[(size_t)ri*FB + lane + 32] = d1*rstd*lnw[lane + 32] + lnb[lane + 32];
    out[(size_t)ri*FB + lane + 64] = d2*rstd*lnw[lane + 64] + lnb[lane + 64];
    out[(size_t)ri*FB + lane + 96] = d3*rstd*lnw[lane + 96] + lnb[lane + 96];
}

extern "C" void kernel_launch(void* const* d_in, const int* in_sizes, int n_in,
                              void* d_out, int out_size) {
    const float* R    = (const float*)d_in[0];
    const float* tv   = (const float*)d_in[1];
    const float* pCB  = (const float*)d_in[2];
    const float* x    = (const float*)d_in[3];
    const float* z    = (const float*)d_in[4];
    const void*  mask = d_in[5];
    const float* Wq   = (const float*)d_in[6];
    const float* Wk   = (const float*)d_in[7];
    const float* Wv   = (const float*)d_in[8];
    const float* Wpb  = (const float*)d_in[9];
    const float* gr   = (const float*)d_in[10];
    const float* Wout = (const float*)d_in[11];
    const float* bo   = (const float*)d_in[12];
    const float* lnw  = (const float*)d_in[13];
    const float* lnb  = (const float*)d_in[14];
    float* out = (float*)d_out;

    decode_mask_kernel<<<1, NL>>>(mask);
    prepw_kernel<<<FB, 256>>>(Wout);
    qkv_kernel<<<NL/8, 576>>>(x, Wq, Wk, Wv);
    qk_kernel<<<NH*64, 256>>>();
    pair_softmax_kernel<<<NL, 256>>>(pCB, z, Wpb, gr);
    p2n_kernel<<<NL, 256, (2*TJ*CB + 2*TJ*16)*sizeof(float)>>>(z);   // 40960 B
    av_kernel<<<NH*8, 320>>>(pCB);
    spatial_kernel<<<NL*HB/256, 256>>>(R, tv);
    proj_kernel<<<128, 256>>>(x, bo);
    ln_kernel<<<NL/8, 256>>>(lnw, lnb, out);
}

// round 9
// speedup vs baseline: 2.6768x; 1.0455x over previous
#include <cuda_runtime.h>
#include <math.h>

#define NB 2
#define LB 512
#define FB 128
#define CB 64
#define HB 12
#define DB 16
#define NL (NB*LB)               // 1024
#define NH (NB*HB)               // 24
#define FEAT 1044
#define FEATP 1088
#define INFV 100000.0f
#define SQ29V 0.47140452079103173f
#define SCALEV 0.57735026918962576f

__device__ float g_qh[(size_t)NH*LB*DB];     // [n][h][i][d]
__device__ float g_kh[(size_t)NH*LB*DB];
__device__ float g_vh[(size_t)NH*LB*DB];
__device__ int   g_mask[NL];
__device__ float g_alpha[(size_t)NH*LB*LB];    // node logits -> alpha [n][h][i][j]
__device__ float g_accP[(size_t)NH*LB*3];
__device__ float g_featsP[(size_t)NL*FEATP];
__device__ float g_WoutP[(size_t)FB*FEATP];
__device__ float g_y[(size_t)NL*FB];

__device__ __forceinline__ void cp_async16(void* smem_dst, const void* gmem_src) {
    unsigned s = (unsigned)__cvta_generic_to_shared(smem_dst);
    asm volatile("cp.async.cg.shared.global [%0], [%1], 16;\n" :: "r"(s), "l"(gmem_src));
}
#define CP_COMMIT() asm volatile("cp.async.commit_group;\n")
#define CP_WAIT1()  asm volatile("cp.async.wait_group 1;\n")
#define CP_WAIT0()  asm volatile("cp.async.wait_group 0;\n")

// ---------------------------------------------------------------------------
// A: decode mask of ambiguous serialized dtype (bool/int32/fp32).
// ---------------------------------------------------------------------------
__global__ void decode_mask_kernel(const void* __restrict__ mraw) {
    __shared__ int cnt[4];
    int t = threadIdx.x;
    if (t < 4) cnt[t] = 0;
    __syncthreads();
    const unsigned char* b = (const unsigned char*)mraw;
    unsigned char v = b[t];
    if (v) atomicAdd(&cnt[t & 3], 1);
    __syncthreads();
    int m;
    if (cnt[1] | cnt[2] | cnt[3]) {
        if (cnt[0]) m = (b[t] != 0);
        else        m = (((const float*)mraw)[t] != 0.0f);
    } else {
        if (cnt[0]) m = (((const int*)mraw)[t] != 0);
        else        m = 0;
    }
    g_mask[t] = m;
}

// ---------------------------------------------------------------------------
// A2: zero-padded Wout copy.
// ---------------------------------------------------------------------------
__global__ void prepw_kernel(const float* __restrict__ Wout) {
    int f = blockIdx.x;
    for (int k = threadIdx.x; k < FEATP; k += 256)
        g_WoutP[(size_t)f*FEATP + k] = (k < FEAT) ? Wout[(size_t)f*FEAT + k] : 0.f;
}

// ---------------------------------------------------------------------------
// B: QKV projection -> per-head layouts [n][h][idx][d].
// ---------------------------------------------------------------------------
__global__ __launch_bounds__(576) void qkv_kernel(
    const float* __restrict__ x,
    const float* __restrict__ Wq,
    const float* __restrict__ Wk,
    const float* __restrict__ Wv)
{
    __shared__ float xs[8][FB];
    int t = threadIdx.x;
    int r0 = blockIdx.x * 8;
    for (int idx = t; idx < 8*FB; idx += 576)
        xs[idx >> 7][idx & 127] = x[(size_t)r0*FB + idx];
    __syncthreads();

    int which = t / 192;
    int o = t - which*192;
    const float* W = (which == 0) ? Wq : (which == 1) ? Wk : Wv;
    float* outp    = (which == 0) ? g_qh : (which == 1) ? g_kh : g_vh;
    const float4* W4 = (const float4*)(W + (size_t)o*FB);

    float acc[8];
#pragma unroll
    for (int r = 0; r < 8; r++) acc[r] = 0.f;
    for (int kk = 0; kk < FB/4; kk++) {
        float4 w = __ldg(&W4[kk]);
#pragma unroll
        for (int r = 0; r < 8; r++) {
            float4 xv = *(const float4*)&xs[r][kk*4];
            acc[r] += w.x*xv.x + w.y*xv.y + w.z*xv.z + w.w*xv.w;
        }
    }
    int h = o >> 4, d = o & 15;
#pragma unroll
    for (int r = 0; r < 8; r++) {
        int row = r0 + r;
        int n = row >> 9, i = row & 511;
        outp[((size_t)(n*HB + h)*LB + i)*DB + d] = acc[r];
    }
}

// ---------------------------------------------------------------------------
// C1: node logits GEMM. Per (n,h): [512x16]x[16x512] -> g_alpha (raw dots).
// ---------------------------------------------------------------------------
__global__ __launch_bounds__(256) void qk_kernel()
{
    __shared__ float Qs[64*17], Ks[64*17];
    int b = blockIdx.x;
    int nh = b >> 6, tile = b & 63;
    int i0 = (tile >> 3)*64, j0 = (tile & 7)*64;
    int t = threadIdx.x;
    {
        int r = t >> 2, c4 = t & 3;
        float4 qv = *(const float4*)(g_qh + ((size_t)nh*LB + i0 + r)*DB + c4*4);
        Qs[r*17+c4*4+0]=qv.x; Qs[r*17+c4*4+1]=qv.y; Qs[r*17+c4*4+2]=qv.z; Qs[r*17+c4*4+3]=qv.w;
        float4 kv = *(const float4*)(g_kh + ((size_t)nh*LB + j0 + r)*DB + c4*4);
        Ks[r*17+c4*4+0]=kv.x; Ks[r*17+c4*4+1]=kv.y; Ks[r*17+c4*4+2]=kv.z; Ks[r*17+c4*4+3]=kv.w;
    }
    __syncthreads();
    int ti = t >> 4, tj = t & 15;
    float acc[4][4];
#pragma unroll
    for (int a = 0; a < 4; a++)
#pragma unroll
        for (int bb = 0; bb < 4; bb++) acc[a][bb] = 0.f;
    const float* Qb = Qs + (ti*4)*17;
    const float* Kb = Ks + (tj*4)*17;
#pragma unroll
    for (int d = 0; d < 16; d++) {
        float q0=Qb[d], q1=Qb[17+d], q2=Qb[34+d], q3=Qb[51+d];
        float k0=Kb[d], k1=Kb[17+d], k2=Kb[34+d], k3=Kb[51+d];
        acc[0][0]+=q0*k0; acc[0][1]+=q0*k1; acc[0][2]+=q0*k2; acc[0][3]+=q0*k3;
        acc[1][0]+=q1*k0; acc[1][1]+=q1*k1; acc[1][2]+=q1*k2; acc[1][3]+=q1*k3;
        acc[2][0]+=q2*k0; acc[2][1]+=q2*k1; acc[2][2]+=q2*k2; acc[2][3]+=q2*k3;
        acc[3][0]+=q3*k0; acc[3][1]+=q3*k1; acc[3][2]+=q3*k2; acc[3][3]+=q3*k3;
    }
    float* outb = g_alpha + ((size_t)nh*LB + i0 + ti*4)*LB + j0 + tj*4;
#pragma unroll
    for (int k = 0; k < 4; k++) {
        float4 o = make_float4(acc[k][0], acc[k][1], acc[k][2], acc[k][3]);
        *(float4*)(outb + (size_t)k*LB) = o;
    }
}

// ---------------------------------------------------------------------------
// C2: FUSED pair-bias + softmax + alpha·z per (n,i).
// Pass A streams z (DRAM) computing logits into lg[j][12]; softmax in smem
// (alpha also exported to g_alpha for av_kernel); pass B re-reads the SAME
// z row (L2 hit) accumulating alpha·z in registers. No intermediate global
// alpha-packed buffer, z DRAM traffic halved vs split kernels.
// ---------------------------------------------------------------------------
__global__ __launch_bounds__(256) void fused_pz_kernel(
    const float* __restrict__ pCB,
    const float* __restrict__ z,
    const float* __restrict__ Wpb,
    const float* __restrict__ gamma_raw)
{
    __shared__ __align__(16) float lg[LB*HB];   // [j][12], 24 KB
    __shared__ float4 WpbV[HB*16];              // 3 KB
    __shared__ float coefH[HB];
    __shared__ float pci[3];
    __shared__ int rowValid;

    int ni = blockIdx.x;
    int n = ni >> 9, i = ni & 511;
    int t = threadIdx.x;

    if (t < 192) WpbV[t] = __ldg(((const float4*)Wpb) + t);
    if (t < HB) {
        float g = gamma_raw[t];
        coefH[t] = -log1pf(__expf(g)) * SQ29V * 0.5f;
    }
    if (t < 3) pci[t] = pCB[(size_t)ni*3 + t];
    if (t == 0) rowValid = g_mask[ni];
    __syncthreads();

    const size_t zrow = (size_t)ni * LB * CB;
    const size_t lbase0 = (size_t)(n*HB)*LB*LB + (size_t)i*LB;

    // ---- pass A: logits ----
#pragma unroll
    for (int rep = 0; rep < 2; rep++) {
        int j = t + rep*256;
        const float* pj = pCB + (size_t)(n*LB + j)*3;
        float dx = pj[0]-pci[0], dy = pj[1]-pci[1], dz = pj[2]-pci[2];
        float d2 = dx*dx + dy*dy + dz*dz;
        float mf = (rowValid && g_mask[n*LB + j]) ? 0.f : -INFV;

        float acc[12];
#pragma unroll
        for (int h = 0; h < 12; h++)
            acc[h] = __ldg(g_alpha + lbase0 + (size_t)h*LB*LB + j) + coefH[h]*d2;

        const float4* z4 = (const float4*)(z + zrow + (size_t)j*CB);
#pragma unroll
        for (int c4 = 0; c4 < 16; c4++) {
            float4 zv = __ldg(z4 + c4);
#pragma unroll
            for (int h = 0; h < 12; h++) {
                float4 wv = WpbV[h*16 + c4];
                acc[h] += zv.x*wv.x + zv.y*wv.y + zv.z*wv.z + zv.w*wv.w;
            }
        }
        float4* dst = (float4*)(lg + j*12);
        dst[0] = make_float4(acc[0]*SCALEV+mf,  acc[1]*SCALEV+mf,  acc[2]*SCALEV+mf,  acc[3]*SCALEV+mf);
        dst[1] = make_float4(acc[4]*SCALEV+mf,  acc[5]*SCALEV+mf,  acc[6]*SCALEV+mf,  acc[7]*SCALEV+mf);
        dst[2] = make_float4(acc[8]*SCALEV+mf,  acc[9]*SCALEV+mf,  acc[10]*SCALEV+mf, acc[11]*SCALEV+mf);
    }
    __syncthreads();

    // ---- softmax per head (alpha normalized; Σα = 1, or 0 for invalid) ----
    int wid = t >> 5, lane = t & 31;
    for (int h = wid; h < HB; h += 8) {
        float m = -INFINITY;
        for (int jj = lane; jj < LB; jj += 32) m = fmaxf(m, lg[jj*12 + h]);
#pragma unroll
        for (int off = 16; off; off >>= 1) m = fmaxf(m, __shfl_xor_sync(0xffffffffu, m, off));
        float s = 0.f;
        for (int jj = lane; jj < LB; jj += 32) {
            float e = __expf(lg[jj*12 + h] - m);
            s += e; lg[jj*12 + h] = e;
        }
#pragma unroll
        for (int off = 16; off; off >>= 1) s += __shfl_xor_sync(0xffffffffu, s, off);
        float inv = rowValid ? (1.f/s) : 0.f;
        float* ga = g_alpha + lbase0 + (size_t)h*LB*LB;
        for (int jj = lane; jj < LB; jj += 32) {
            float a = lg[jj*12 + h]*inv;
            lg[jj*12 + h] = a;
            ga[jj] = a;
        }
    }
    __syncthreads();

    // ---- pass B: alpha · z (z re-read -> L2 hits) ----
    float2 az[12];
#pragma unroll
    for (int h = 0; h < 12; h++) az[h] = make_float2(0.f, 0.f);
    const int cq = t & 31, jq = t >> 5;
    const float2* z2 = (const float2*)(z + zrow);

#pragma unroll 4
    for (int jj = 0; jj < 64; jj++) {
        int j = jq*64 + jj;
        float2 zv = __ldg(z2 + (size_t)j*32 + cq);
        const float4* p4 = (const float4*)(lg + j*12);
        float4 pa = p4[0], pb = p4[1], pc = p4[2];
        az[0].x  += pa.x*zv.x; az[0].y  += pa.x*zv.y;
        az[1].x  += pa.y*zv.x; az[1].y  += pa.y*zv.y;
        az[2].x  += pa.z*zv.x; az[2].y  += pa.z*zv.y;
        az[3].x  += pa.w*zv.x; az[3].y  += pa.w*zv.y;
        az[4].x  += pb.x*zv.x; az[4].y  += pb.x*zv.y;
        az[5].x  += pb.y*zv.x; az[5].y  += pb.y*zv.y;
        az[6].x  += pb.z*zv.x; az[6].y  += pb.z*zv.y;
        az[7].x  += pb.w*zv.x; az[7].y  += pb.w*zv.y;
        az[8].x  += pc.x*zv.x; az[8].y  += pc.x*zv.y;
        az[9].x  += pc.y*zv.x; az[9].y  += pc.y*zv.y;
        az[10].x += pc.z*zv.x; az[10].y += pc.z*zv.y;
        az[11].x += pc.w*zv.x; az[11].y += pc.w*zv.y;
    }
    __syncthreads();   // all alpha reads done; lg reusable as reduce buffer

    float* part = lg;  // [8][768]
#pragma unroll
    for (int h = 0; h < 12; h++)
        ((float2*)(part + jq*768 + h*64))[cq] = az[h];
    __syncthreads();

    float* fo = g_featsP + (size_t)ni*FEATP;
    for (int o = t; o < 768; o += 256) {
        float v = part[o] + part[768+o] + part[1536+o] + part[2304+o]
                + part[3072+o] + part[3840+o] + part[4608+o] + part[5376+o];
        fo[o] = v;
    }
    if (t < FEATP - FEAT) fo[FEAT + t] = 0.f;   // zero pad
}

// ---------------------------------------------------------------------------
// C4: feat_node (alpha·v) + accP (alpha·pCB) per (n,h) as tiled GEMM.
// ---------------------------------------------------------------------------
__global__ __launch_bounds__(320) void av_kernel(const float* __restrict__ pCB)
{
    __shared__ float As[64*65];
    __shared__ float vs[64*16];
    __shared__ float ps[64*4];
    int b = blockIdx.x;
    int nh = b >> 3;
    int i0 = (b & 7)*64;
    int n = nh / HB, h = nh - n*HB;
    int t = threadIdx.x;
    int i_l = t & 63, col = t >> 6;

    float a0 = 0.f, a1 = 0.f, a2 = 0.f, a3 = 0.f;

    for (int jt = 0; jt < 8; jt++) {
        int j0 = jt*64;
        __syncthreads();
        if (t < 256) {
            int r = t >> 2, c16 = t & 3;
            const float4* src = (const float4*)(g_alpha + ((size_t)nh*LB + i0 + r)*LB + j0 + c16*16);
#pragma unroll
            for (int q = 0; q < 4; q++) {
                float4 v = __ldg(src + q);
                int jj = c16*16 + q*4;
                As[(jj+0)*65 + r] = v.x;
                As[(jj+1)*65 + r] = v.y;
                As[(jj+2)*65 + r] = v.z;
                As[(jj+3)*65 + r] = v.w;
            }
            *(float4*)(vs + r*16 + c16*4) =
                *(const float4*)(g_vh + ((size_t)nh*LB + j0 + r)*DB + c16*4);
        } else {
            int tt = t - 256;
            const float* pb = pCB + (size_t)(n*LB + j0 + tt)*3;
            ps[tt*4+0] = pb[0]; ps[tt*4+1] = pb[1]; ps[tt*4+2] = pb[2]; ps[tt*4+3] = 0.f;
        }
        __syncthreads();

        if (col < 4) {
#pragma unroll 8
            for (int j = 0; j < 64; j++) {
                float a = As[j*65 + i_l];
                float4 vv = *(float4*)(vs + j*16 + col*4);
                a0 += a*vv.x; a1 += a*vv.y; a2 += a*vv.z; a3 += a*vv.w;
            }
        } else {
#pragma unroll 8
            for (int j = 0; j < 64; j++) {
                float a = As[j*65 + i_l];
                float4 pp = *(float4*)(ps + j*4);
                a0 += a*pp.x; a1 += a*pp.y; a2 += a*pp.z;
            }
        }
    }

    int i = i0 + i_l;
    if (col < 4) {
        float* fo = g_featsP + (size_t)(n*LB + i)*FEATP + 768 + h*16 + col*4;
        fo[0] = a0; fo[1] = a1; fo[2] = a2; fo[3] = a3;
    } else {
        float* ap = g_accP + ((size_t)nh*LB + i)*3;
        ap[0] = a0; ap[1] = a1; ap[2] = a2;
    }
}

// ---------------------------------------------------------------------------
// C5: spatial features. One thread per (n,i,h).
// ---------------------------------------------------------------------------
__global__ __launch_bounds__(256) void spatial_kernel(
    const float* __restrict__ R,
    const float* __restrict__ tvec)
{
    int gid = blockIdx.x*256 + threadIdx.x;
    int ni = gid / HB, h = gid - ni*HB;
    int n = ni >> 9;
    const float* ap = g_accP + ((size_t)(n*HB + h)*LB + (ni & 511))*3;
    float a0 = ap[0] - tvec[(size_t)ni*3+0];
    float a1 = ap[1] - tvec[(size_t)ni*3+1];
    float a2 = ap[2] - tvec[(size_t)ni*3+2];
    const float* Rp = R + (size_t)ni*9;
    float l0 = Rp[0]*a0 + Rp[3]*a1 + Rp[6]*a2;
    float l1 = Rp[1]*a0 + Rp[4]*a1 + Rp[7]*a2;
    float l2 = Rp[2]*a0 + Rp[5]*a1 + Rp[8]*a2;
    float dist = sqrtf(l0*l0 + l1*l1 + l2*l2);
    float idn = 1.0f / (dist + 1e-4f);
    float* fo = g_featsP + (size_t)ni*FEATP + 960;
    fo[h*3+0] = l0; fo[h*3+1] = l1; fo[h*3+2] = l2;
    fo[36 + h] = dist;
    fo[48 + h*3+0] = l0*idn; fo[48 + h*3+1] = l1*idn; fo[48 + h*3+2] = l2*idn;
}

// ---------------------------------------------------------------------------
// D1: output projection tiled GEMM.
// ---------------------------------------------------------------------------
#define KT 64
#define NKT (FEATP/KT)
#define TS 68

__global__ __launch_bounds__(256) void proj_kernel(
    const float* __restrict__ x,
    const float* __restrict__ bout)
{
    __shared__ float fsT[2][32*TS];
    __shared__ float wsT[2][32*TS];
    int t = threadIdx.x;
    int mb = blockIdx.x & 31, fb = blockIdx.x >> 5;
    int r0 = mb*32, f0 = fb*32;

    const float* fbase = g_featsP + (size_t)r0*FEATP;
    const float* wbase = g_WoutP  + (size_t)f0*FEATP;
    {
#pragma unroll
        for (int rep = 0; rep < 2; rep++) {
            int idx = t + rep*256;
            int row = idx >> 4, col = idx & 15;
            cp_async16(&fsT[0][row*TS + col*4], fbase + (size_t)row*FEATP + col*4);
            cp_async16(&wsT[0][row*TS + col*4], wbase + (size_t)row*FEATP + col*4);
        }
        CP_COMMIT();
    }

    int tr = t >> 4, tf = t & 15;
    float a00 = 0.f, a01 = 0.f, a10 = 0.f, a11 = 0.f;
    for (int kt = 0; kt < NKT; kt++) {
        int buf = kt & 1;
        if (kt < NKT-1) {
#pragma unroll
            for (int rep = 0; rep < 2; rep++) {
                int idx = t + rep*256;
                int row = idx >> 4, col = idx & 15;
                cp_async16(&fsT[buf^1][row*TS + col*4],
                           fbase + (size_t)row*FEATP + (kt+1)*KT + col*4);
                cp_async16(&wsT[buf^1][row*TS + col*4],
                           wbase + (size_t)row*FEATP + (kt+1)*KT + col*4);
            }
            CP_COMMIT();
            CP_WAIT1();
        } else {
            CP_WAIT0();
        }
        __syncthreads();

        const float4* fr0 = (const float4*)&fsT[buf][(tr*2  )*TS];
        const float4* fr1 = (const float4*)&fsT[buf][(tr*2+1)*TS];
        const float4* wr0 = (const float4*)&wsT[buf][(tf*2  )*TS];
        const float4* wr1 = (const float4*)&wsT[buf][(tf*2+1)*TS];
#pragma unroll
        for (int k4 = 0; k4 < KT/4; k4++) {
            float4 xa = fr0[k4], xb = fr1[k4];
            float4 wa = wr0[k4], wb = wr1[k4];
            a00 += xa.x*wa.x + xa.y*wa.y + xa.z*wa.z + xa.w*wa.w;
            a01 += xa.x*wb.x + xa.y*wb.y + xa.z*wb.z + xa.w*wb.w;
            a10 += xb.x*wa.x + xb.y*wa.y + xb.z*wa.z + xb.w*wa.w;
            a11 += xb.x*wb.x + xb.y*wb.y + xb.z*wb.z + xb.w*wb.w;
        }
        __syncthreads();
    }

    int ri0 = r0 + tr*2, ri1 = ri0 + 1;
    int fA = f0 + tf*2, fB2 = fA + 1;
    float bA = __ldg(&bout[fA]), bB = __ldg(&bout[fB2]);
    int m0 = g_mask[ri0], m1 = g_mask[ri1];
    g_y[(size_t)ri0*FB + fA ] = x[(size_t)ri0*FB + fA ] + (m0 ? (a00 + bA) : 0.f);
    g_y[(size_t)ri0*FB + fB2] = x[(size_t)ri0*FB + fB2] + (m0 ? (a01 + bB) : 0.f);
    g_y[(size_t)ri1*FB + fA ] = x[(size_t)ri1*FB + fA ] + (m1 ? (a10 + bA) : 0.f);
    g_y[(size_t)ri1*FB + fB2] = x[(size_t)ri1*FB + fB2] + (m1 ? (a11 + bB) : 0.f);
}

// ---------------------------------------------------------------------------
// D2: LayerNorm.
// ---------------------------------------------------------------------------
__global__ __launch_bounds__(256) void ln_kernel(
    const float* __restrict__ lnw,
    const float* __restrict__ lnb,
    float* __restrict__ out)
{
    int t = threadIdx.x;
    int wid = t >> 5, lane = t & 31;
    int ri = blockIdx.x * 8 + wid;
    const float* yr = g_y + (size_t)ri*FB;
    float v0 = yr[lane], v1 = yr[lane+32], v2 = yr[lane+64], v3 = yr[lane+96];
    float s = v0 + v1 + v2 + v3;
#pragma unroll
    for (int off = 16; off; off >>= 1) s += __shfl_xor_sync(0xffffffffu, s, off);
    float mu = s * (1.0f/128.0f);
    float d0 = v0-mu, d1 = v1-mu, d2 = v2-mu, d3 = v3-mu;
    float sq = d0*d0 + d1*d1 + d2*d2 + d3*d3;
#pragma unroll
    for (int off = 16; off; off >>= 1) sq += __shfl_xor_sync(0xffffffffu, sq, off);
    float rstd = rsqrtf(sq * (1.0f/128.0f) + 1e-5f);
    out[(size_t)ri*FB + lane     ] = d0*rstd*lnw[lane     ] + lnb[lane     ];
    out[(size_t)ri*FB + lane + 32] = d1*rstd*lnw[lane + 32] + lnb[lane + 32];
    out[(size_t)ri*FB + lane + 64] = d2*rstd*lnw[lane + 64] + lnb[lane + 64];
    out[(size_t)ri*FB + lane + 96] = d3*rstd*lnw[lane + 96] + lnb[lane + 96];
}

extern "C" void kernel_launch(void* const* d_in, const int* in_sizes, int n_in,
                              void* d_out, int out_size) {
    const float* R    = (const float*)d_in[0];
    const float* tv   = (const float*)d_in[1];
    const float* pCB  = (const float*)d_in[2];
    const float* x    = (const float*)d_in[3];
    const float* z    = (const float*)d_in[4];
    const void*  mask = d_in[5];
    const float* Wq   = (const float*)d_in[6];
    const float* Wk   = (const float*)d_in[7];
    const float* Wv   = (const float*)d_in[8];
    const float* Wpb  = (const float*)d_in[9];
    const float* gr   = (const float*)d_in[10];
    const float* Wout = (const float*)d_in[11];
    const float* bo   = (const float*)d_in[12];
    const float* lnw  = (const float*)d_in[13];
    const float* lnb  = (const float*)d_in[14];
    float* out = (float*)d_out;

    decode_mask_kernel<<<1, NL>>>(mask);
    prepw_kernel<<<FB, 256>>>(Wout);
    qkv_kernel<<<NL/8, 576>>>(x, Wq, Wk, Wv);
    qk_kernel<<<NH*64, 256>>>();
    fused_pz_kernel<<<NL, 256>>>(pCB, z, Wpb, gr);
    av_kernel<<<NH*8, 320>>>(pCB);
    spatial_kernel<<<NL*HB/256, 256>>>(R, tv);
    proj_kernel<<<128, 256>>>(x, bo);
    ln_kernel<<<NL/8, 256>>>(lnw, lnb, out);
}

// round 11
// speedup vs baseline: 2.9795x; 1.1131x over previous
#include <cuda_runtime.h>
#include <math.h>

#define NB 2
#define LB 512
#define FB 128
#define CB 64
#define HB 12
#define DB 16
#define NL (NB*LB)               // 1024
#define NH (NB*HB)               // 24
#define FEAT 1044
#define FEATP 1088
#define INFV 100000.0f
#define SQ29V 0.47140452079103173f
#define SCALEV 0.57735026918962576f

__device__ float g_qh[(size_t)NH*LB*DB];     // [n][h][i][d]  (q pre-scaled by SCALEV)
__device__ float g_kh[(size_t)NH*LB*DB];
__device__ float g_vh[(size_t)NH*LB*DB];
__device__ int   g_mask[NL];
__device__ float g_alpha[(size_t)NH*LB*LB];  // node logits -> unnormalized exp(alpha)
__device__ float g_inv[(size_t)NL*HB];       // 1/S per (n,i,h); 0 for invalid rows
__device__ float g_accP[(size_t)NH*LB*3];
__device__ float g_featsP[(size_t)NL*FEATP];
__device__ float g_WoutP[(size_t)FB*FEATP];
__device__ float g_y[(size_t)NL*FB];

__device__ __forceinline__ void cp_async16(void* smem_dst, const void* gmem_src) {
    unsigned s = (unsigned)__cvta_generic_to_shared(smem_dst);
    asm volatile("cp.async.cg.shared.global [%0], [%1], 16;\n" :: "r"(s), "l"(gmem_src));
}
#define CP_COMMIT() asm volatile("cp.async.commit_group;\n")
#define CP_WAIT1()  asm volatile("cp.async.wait_group 1;\n")
#define CP_WAIT0()  asm volatile("cp.async.wait_group 0;\n")

// ---------------------------------------------------------------------------
// A: decode mask of ambiguous serialized dtype (bool/int32/fp32).
// ---------------------------------------------------------------------------
__global__ void decode_mask_kernel(const void* __restrict__ mraw) {
    __shared__ int cnt[4];
    int t = threadIdx.x;
    if (t < 4) cnt[t] = 0;
    __syncthreads();
    const unsigned char* b = (const unsigned char*)mraw;
    unsigned char v = b[t];
    if (v) atomicAdd(&cnt[t & 3], 1);
    __syncthreads();
    int m;
    if (cnt[1] | cnt[2] | cnt[3]) {
        if (cnt[0]) m = (b[t] != 0);
        else        m = (((const float*)mraw)[t] != 0.0f);
    } else {
        if (cnt[0]) m = (((const int*)mraw)[t] != 0);
        else        m = 0;
    }
    g_mask[t] = m;
}

// ---------------------------------------------------------------------------
// A2: zero-padded Wout copy.
// ---------------------------------------------------------------------------
__global__ void prepw_kernel(const float* __restrict__ Wout) {
    int f = blockIdx.x;
    for (int k = threadIdx.x; k < FEATP; k += 256)
        g_WoutP[(size_t)f*FEATP + k] = (k < FEAT) ? Wout[(size_t)f*FEAT + k] : 0.f;
}

// ---------------------------------------------------------------------------
// B: QKV projection -> per-head layouts [n][h][idx][d]. q scaled by SCALEV
// so downstream logits need no extra multiply.
// ---------------------------------------------------------------------------
__global__ __launch_bounds__(576) void qkv_kernel(
    const float* __restrict__ x,
    const float* __restrict__ Wq,
    const float* __restrict__ Wk,
    const float* __restrict__ Wv)
{
    __shared__ float xs[8][FB];
    int t = threadIdx.x;
    int r0 = blockIdx.x * 8;
    for (int idx = t; idx < 8*FB; idx += 576)
        xs[idx >> 7][idx & 127] = x[(size_t)r0*FB + idx];
    __syncthreads();

    int which = t / 192;
    int o = t - which*192;
    const float* W = (which == 0) ? Wq : (which == 1) ? Wk : Wv;
    float* outp    = (which == 0) ? g_qh : (which == 1) ? g_kh : g_vh;
    const float4* W4 = (const float4*)(W + (size_t)o*FB);

    float acc[8];
#pragma unroll
    for (int r = 0; r < 8; r++) acc[r] = 0.f;
    for (int kk = 0; kk < FB/4; kk++) {
        float4 w = __ldg(&W4[kk]);
#pragma unroll
        for (int r = 0; r < 8; r++) {
            float4 xv = *(const float4*)&xs[r][kk*4];
            acc[r] += w.x*xv.x + w.y*xv.y + w.z*xv.z + w.w*xv.w;
        }
    }
    float scale = (which == 0) ? SCALEV : 1.0f;
    int h = o >> 4, d = o & 15;
#pragma unroll
    for (int r = 0; r < 8; r++) {
        int row = r0 + r;
        int n = row >> 9, i = row & 511;
        outp[((size_t)(n*HB + h)*LB + i)*DB + d] = acc[r] * scale;
    }
}

// ---------------------------------------------------------------------------
// C1: node logits GEMM. Per (n,h): [512x16]x[16x512] -> g_alpha (scaled dots).
// ---------------------------------------------------------------------------
__global__ __launch_bounds__(256) void qk_kernel()
{
    __shared__ float Qs[64*17], Ks[64*17];
    int b = blockIdx.x;
    int nh = b >> 6, tile = b & 63;
    int i0 = (tile >> 3)*64, j0 = (tile & 7)*64;
    int t = threadIdx.x;
    {
        int r = t >> 2, c4 = t & 3;
        float4 qv = *(const float4*)(g_qh + ((size_t)nh*LB + i0 + r)*DB + c4*4);
        Qs[r*17+c4*4+0]=qv.x; Qs[r*17+c4*4+1]=qv.y; Qs[r*17+c4*4+2]=qv.z; Qs[r*17+c4*4+3]=qv.w;
        float4 kv = *(const float4*)(g_kh + ((size_t)nh*LB + j0 + r)*DB + c4*4);
        Ks[r*17+c4*4+0]=kv.x; Ks[r*17+c4*4+1]=kv.y; Ks[r*17+c4*4+2]=kv.z; Ks[r*17+c4*4+3]=kv.w;
    }
    __syncthreads();
    int ti = t >> 4, tj = t & 15;
    float acc[4][4];
#pragma unroll
    for (int a = 0; a < 4; a++)
#pragma unroll
        for (int bb = 0; bb < 4; bb++) acc[a][bb] = 0.f;
    const float* Qb = Qs + (ti*4)*17;
    const float* Kb = Ks + (tj*4)*17;
#pragma unroll
    for (int d = 0; d < 16; d++) {
        float q0=Qb[d], q1=Qb[17+d], q2=Qb[34+d], q3=Qb[51+d];
        float k0=Kb[d], k1=Kb[17+d], k2=Kb[34+d], k3=Kb[51+d];
        acc[0][0]+=q0*k0; acc[0][1]+=q0*k1; acc[0][2]+=q0*k2; acc[0][3]+=q0*k3;
        acc[1][0]+=q1*k0; acc[1][1]+=q1*k1; acc[1][2]+=q1*k2; acc[1][3]+=q1*k3;
        acc[2][0]+=q2*k0; acc[2][1]+=q2*k1; acc[2][2]+=q2*k2; acc[2][3]+=q2*k3;
        acc[3][0]+=q3*k0; acc[3][1]+=q3*k1; acc[3][2]+=q3*k2; acc[3][3]+=q3*k3;
    }
    float* outb = g_alpha + ((size_t)nh*LB + i0 + ti*4)*LB + j0 + tj*4;
#pragma unroll
    for (int k = 0; k < 4; k++) {
        float4 o = make_float4(acc[k][0], acc[k][1], acc[k][2], acc[k][3]);
        *(float4*)(outb + (size_t)k*LB) = o;
    }
}

// ---------------------------------------------------------------------------
// C2: FUSED pair-bias + exp + sums + alpha·z per (n,i).
// Max-free softmax: logits are bounded (small-scale weights), masked entries
// exp to exactly 0 (same as reference post-shift). Pass A computes
// e = exp(logit) directly while streaming z (DRAM read #1); per-head sums
// give 1/S (deferred normalization, exported via g_inv); pass B re-reads z
// (L2) accumulating e·z, scaling by 1/S at the end.
// ---------------------------------------------------------------------------
__global__ __launch_bounds__(256, 3) void fused_pz_kernel(
    const float* __restrict__ pCB,
    const float* __restrict__ z,
    const float* __restrict__ Wpb,
    const float* __restrict__ gamma_raw)
{
    __shared__ __align__(16) float lg[LB*HB];   // e values [j][12], 24 KB
    __shared__ float4 WpbV[HB*16];              // Wpb * SCALEV
    __shared__ float coefH[HB], invH[HB];
    __shared__ float pci[3];
    __shared__ int rowValid;

    int ni = blockIdx.x;
    int n = ni >> 9, i = ni & 511;
    int t = threadIdx.x;

    if (t < 192) {
        float4 w = __ldg(((const float4*)Wpb) + t);
        WpbV[t] = make_float4(w.x*SCALEV, w.y*SCALEV, w.z*SCALEV, w.w*SCALEV);
    }
    if (t < HB) {
        float g = gamma_raw[t];
        coefH[t] = -log1pf(__expf(g)) * SQ29V * 0.5f * SCALEV;
    }
    if (t < 3) pci[t] = pCB[(size_t)ni*3 + t];
    if (t == 0) rowValid = g_mask[ni];
    __syncthreads();

    const size_t zrow = (size_t)ni * LB * CB;
    const size_t LL = (size_t)LB*LB;
    const size_t lbase0 = (size_t)(n*HB)*LL + (size_t)i*LB;
    const int j0 = t, j1 = t + 256;

    // ---- pass A: logits -> e for j0 and j1 (shared Wpb loads) ----
    float acc0[12], acc1[12];
#pragma unroll
    for (int h = 0; h < 12; h++) {
        acc0[h] = __ldg(g_alpha + lbase0 + (size_t)h*LL + j0);
        acc1[h] = __ldg(g_alpha + lbase0 + (size_t)h*LL + j1);
    }
    float mf0, mf1;
    {
        const float* pj = pCB + (size_t)(n*LB + j0)*3;
        float dx = pj[0]-pci[0], dy = pj[1]-pci[1], dz = pj[2]-pci[2];
        float d2 = dx*dx + dy*dy + dz*dz;
        mf0 = (rowValid && g_mask[n*LB + j0]) ? 0.f : -INFV;
#pragma unroll
        for (int h = 0; h < 12; h++) acc0[h] += coefH[h]*d2;
    }
    {
        const float* pj = pCB + (size_t)(n*LB + j1)*3;
        float dx = pj[0]-pci[0], dy = pj[1]-pci[1], dz = pj[2]-pci[2];
        float d2 = dx*dx + dy*dy + dz*dz;
        mf1 = (rowValid && g_mask[n*LB + j1]) ? 0.f : -INFV;
#pragma unroll
        for (int h = 0; h < 12; h++) acc1[h] += coefH[h]*d2;
    }
    {
        const float4* z40 = (const float4*)(z + zrow + (size_t)j0*CB);
        const float4* z41 = (const float4*)(z + zrow + (size_t)j1*CB);
#pragma unroll 4
        for (int c4 = 0; c4 < 16; c4++) {
            float4 a = __ldg(z40 + c4);
            float4 b = __ldg(z41 + c4);
#pragma unroll
            for (int h = 0; h < 12; h++) {
                float4 wv = WpbV[h*16 + c4];
                acc0[h] += a.x*wv.x + a.y*wv.y + a.z*wv.z + a.w*wv.w;
                acc1[h] += b.x*wv.x + b.y*wv.y + b.z*wv.z + b.w*wv.w;
            }
        }
    }
    // e = exp(logit); store to lg and export unnormalized to g_alpha
    {
        float e0[12], e1[12];
#pragma unroll
        for (int h = 0; h < 12; h++) {
            e0[h] = __expf(acc0[h] + mf0);
            e1[h] = __expf(acc1[h] + mf1);
        }
        float4* d0 = (float4*)(lg + j0*12);
        d0[0] = make_float4(e0[0], e0[1], e0[2],  e0[3]);
        d0[1] = make_float4(e0[4], e0[5], e0[6],  e0[7]);
        d0[2] = make_float4(e0[8], e0[9], e0[10], e0[11]);
        float4* d1 = (float4*)(lg + j1*12);
        d1[0] = make_float4(e1[0], e1[1], e1[2],  e1[3]);
        d1[1] = make_float4(e1[4], e1[5], e1[6],  e1[7]);
        d1[2] = make_float4(e1[8], e1[9], e1[10], e1[11]);
        float* ga = g_alpha + lbase0;
#pragma unroll
        for (int h = 0; h < 12; h++) {
            ga[(size_t)h*LL + j0] = e0[h];
            ga[(size_t)h*LL + j1] = e1[h];
        }
    }
    __syncthreads();

    // ---- per-head sums -> 1/S ----
    int wid = t >> 5, lane = t & 31;
    for (int h = wid; h < HB; h += 8) {
        float s = 0.f;
        for (int jj = lane; jj < LB; jj += 32) s += lg[jj*12 + h];
#pragma unroll
        for (int off = 16; off; off >>= 1) s += __shfl_xor_sync(0xffffffffu, s, off);
        if (lane == 0) {
            float inv = rowValid ? (1.f/s) : 0.f;
            invH[h] = inv;
            g_inv[(size_t)ni*HB + h] = inv;
        }
    }
    __syncthreads();

    // ---- pass B: e · z (z re-read -> L2), normalize at the end ----
    float2 az[12];
#pragma unroll
    for (int h = 0; h < 12; h++) az[h] = make_float2(0.f, 0.f);
    const int cq = t & 31, jq = t >> 5;
    const float2* z2 = (const float2*)(z + zrow);

#pragma unroll 4
    for (int jj = 0; jj < 64; jj++) {
        int j = jq*64 + jj;
        float2 zv = __ldg(z2 + (size_t)j*32 + cq);
        const float4* p4 = (const float4*)(lg + j*12);
        float4 pa = p4[0], pb = p4[1], pc = p4[2];
        az[0].x  += pa.x*zv.x; az[0].y  += pa.x*zv.y;
        az[1].x  += pa.y*zv.x; az[1].y  += pa.y*zv.y;
        az[2].x  += pa.z*zv.x; az[2].y  += pa.z*zv.y;
        az[3].x  += pa.w*zv.x; az[3].y  += pa.w*zv.y;
        az[4].x  += pb.x*zv.x; az[4].y  += pb.x*zv.y;
        az[5].x  += pb.y*zv.x; az[5].y  += pb.y*zv.y;
        az[6].x  += pb.z*zv.x; az[6].y  += pb.z*zv.y;
        az[7].x  += pb.w*zv.x; az[7].y  += pb.w*zv.y;
        az[8].x  += pc.x*zv.x; az[8].y  += pc.x*zv.y;
        az[9].x  += pc.y*zv.x; az[9].y  += pc.y*zv.y;
        az[10].x += pc.z*zv.x; az[10].y += pc.z*zv.y;
        az[11].x += pc.w*zv.x; az[11].y += pc.w*zv.y;
    }
#pragma unroll
    for (int h = 0; h < 12; h++) {
        float inv = invH[h];
        az[h].x *= inv; az[h].y *= inv;
    }
    __syncthreads();   // all e reads done; lg reusable as reduce buffer

    float* part = lg;  // [8][768]
#pragma unroll
    for (int h = 0; h < 12; h++)
        ((float2*)(part + jq*768 + h*64))[cq] = az[h];
    __syncthreads();

    float* fo = g_featsP + (size_t)ni*FEATP;
    for (int o = t; o < 768; o += 256) {
        float v = part[o] + part[768+o] + part[1536+o] + part[2304+o]
                + part[3072+o] + part[3840+o] + part[4608+o] + part[5376+o];
        fo[o] = v;
    }
    if (t < FEATP - FEAT) fo[FEAT + t] = 0.f;   // zero pad
}

// ---------------------------------------------------------------------------
// C4: feat_node (alpha·v) + accP (alpha·pCB) per (n,h); alpha is unnormalized
// e from g_alpha, scaled by g_inv at the end.
// ---------------------------------------------------------------------------
__global__ __launch_bounds__(320) void av_kernel(const float* __restrict__ pCB)
{
    __shared__ float As[64*65];
    __shared__ float vs[64*16];
    __shared__ float ps[64*4];
    int b = blockIdx.x;
    int nh = b >> 3;
    int i0 = (b & 7)*64;
    int n = nh / HB, h = nh - n*HB;
    int t = threadIdx.x;
    int i_l = t & 63, col = t >> 6;

    float a0 = 0.f, a1 = 0.f, a2 = 0.f, a3 = 0.f;

    for (int jt = 0; jt < 8; jt++) {
        int j0 = jt*64;
        __syncthreads();
        if (t < 256) {
            int r = t >> 2, c16 = t & 3;
            const float4* src = (const float4*)(g_alpha + ((size_t)nh*LB + i0 + r)*LB + j0 + c16*16);
#pragma unroll
            for (int q = 0; q < 4; q++) {
                float4 v = __ldg(src + q);
                int jj = c16*16 + q*4;
                As[(jj+0)*65 + r] = v.x;
                As[(jj+1)*65 + r] = v.y;
                As[(jj+2)*65 + r] = v.z;
                As[(jj+3)*65 + r] = v.w;
            }
            *(float4*)(vs + r*16 + c16*4) =
                *(const float4*)(g_vh + ((size_t)nh*LB + j0 + r)*DB + c16*4);
        } else {
            int tt = t - 256;
            const float* pb = pCB + (size_t)(n*LB + j0 + tt)*3;
            ps[tt*4+0] = pb[0]; ps[tt*4+1] = pb[1]; ps[tt*4+2] = pb[2]; ps[tt*4+3] = 0.f;
        }
        __syncthreads();

        if (col < 4) {
#pragma unroll 8
            for (int j = 0; j < 64; j++) {
                float a = As[j*65 + i_l];
                float4 vv = *(float4*)(vs + j*16 + col*4);
                a0 += a*vv.x; a1 += a*vv.y; a2 += a*vv.z; a3 += a*vv.w;
            }
        } else {
#pragma unroll 8
            for (int j = 0; j < 64; j++) {
                float a = As[j*65 + i_l];
                float4 pp = *(float4*)(ps + j*4);
                a0 += a*pp.x; a1 += a*pp.y; a2 += a*pp.z;
            }
        }
    }

    int i = i0 + i_l;
    float inv = __ldg(&g_inv[(size_t)(n*LB + i)*HB + h]);
    if (col < 4) {
        float* fo = g_featsP + (size_t)(n*LB + i)*FEATP + 768 + h*16 + col*4;
        fo[0] = a0*inv; fo[1] = a1*inv; fo[2] = a2*inv; fo[3] = a3*inv;
    } else {
        float* ap = g_accP + ((size_t)nh*LB + i)*3;
        ap[0] = a0*inv; ap[1] = a1*inv; ap[2] = a2*inv;
    }
}

// ---------------------------------------------------------------------------
// C5: spatial features. One thread per (n,i,h).
// ---------------------------------------------------------------------------
__global__ __launch_bounds__(256) void spatial_kernel(
    const float* __restrict__ R,
    const float* __restrict__ tvec)
{
    int gid = blockIdx.x*256 + threadIdx.x;
    int ni = gid / HB, h = gid - ni*HB;
    int n = ni >> 9;
    const float* ap = g_accP + ((size_t)(n*HB + h)*LB + (ni & 511))*3;
    float a0 = ap[0] - tvec[(size_t)ni*3+0];
    float a1 = ap[1] - tvec[(size_t)ni*3+1];
    float a2 = ap[2] - tvec[(size_t)ni*3+2];
    const float* Rp = R + (size_t)ni*9;
    float l0 = Rp[0]*a0 + Rp[3]*a1 + Rp[6]*a2;
    float l1 = Rp[1]*a0 + Rp[4]*a1 + Rp[7]*a2;
    float l2 = Rp[2]*a0 + Rp[5]*a1 + Rp[8]*a2;
    float dist = sqrtf(l0*l0 + l1*l1 + l2*l2);
    float idn = 1.0f / (dist + 1e-4f);
    float* fo = g_featsP + (size_t)ni*FEATP + 960;
    fo[h*3+0] = l0; fo[h*3+1] = l1; fo[h*3+2] = l2;
    fo[36 + h] = dist;
    fo[48 + h*3+0] = l0*idn; fo[48 + h*3+1] = l1*idn; fo[48 + h*3+2] = l2*idn;
}

// ---------------------------------------------------------------------------
// D1: output projection tiled GEMM.
// ---------------------------------------------------------------------------
#define KT 64
#define NKT (FEATP/KT)
#define TS 68

__global__ __launch_bounds__(256) void proj_kernel(
    const float* __restrict__ x,
    const float* __restrict__ bout)
{
    __shared__ float fsT[2][32*TS];
    __shared__ float wsT[2][32*TS];
    int t = threadIdx.x;
    int mb = blockIdx.x & 31, fb = blockIdx.x >> 5;
    int r0 = mb*32, f0 = fb*32;

    const float* fbase = g_featsP + (size_t)r0*FEATP;
    const float* wbase = g_WoutP  + (size_t)f0*FEATP;
    {
#pragma unroll
        for (int rep = 0; rep < 2; rep++) {
            int idx = t + rep*256;
            int row = idx >> 4, col = idx & 15;
            cp_async16(&fsT[0][row*TS + col*4], fbase + (size_t)row*FEATP + col*4);
            cp_async16(&wsT[0][row*TS + col*4], wbase + (size_t)row*FEATP + col*4);
        }
        CP_COMMIT();
    }

    int tr = t >> 4, tf = t & 15;
    float a00 = 0.f, a01 = 0.f, a10 = 0.f, a11 = 0.f;
    for (int kt = 0; kt < NKT; kt++) {
        int buf = kt & 1;
        if (kt < NKT-1) {
#pragma unroll
            for (int rep = 0; rep < 2; rep++) {
                int idx = t + rep*256;
                int row = idx >> 4, col = idx & 15;
                cp_async16(&fsT[buf^1][row*TS + col*4],
                           fbase + (size_t)row*FEATP + (kt+1)*KT + col*4);
                cp_async16(&wsT[buf^1][row*TS + col*4],
                           wbase + (size_t)row*FEATP + (kt+1)*KT + col*4);
            }
            CP_COMMIT();
            CP_WAIT1();
        } else {
            CP_WAIT0();
        }
        __syncthreads();

        const float4* fr0 = (const float4*)&fsT[buf][(tr*2  )*TS];
        const float4* fr1 = (const float4*)&fsT[buf][(tr*2+1)*TS];
        const float4* wr0 = (const float4*)&wsT[buf][(tf*2  )*TS];
        const float4* wr1 = (const float4*)&wsT[buf][(tf*2+1)*TS];
#pragma unroll
        for (int k4 = 0; k4 < KT/4; k4++) {
            float4 xa = fr0[k4], xb = fr1[k4];
            float4 wa = wr0[k4], wb = wr1[k4];
            a00 += xa.x*wa.x + xa.y*wa.y + xa.z*wa.z + xa.w*wa.w;
            a01 += xa.x*wb.x + xa.y*wb.y + xa.z*wb.z + xa.w*wb.w;
            a10 += xb.x*wa.x + xb.y*wa.y + xb.z*wa.z + xb.w*wa.w;
            a11 += xb.x*wb.x + xb.y*wb.y + xb.z*wb.z + xb.w*wb.w;
        }
        __syncthreads();
    }

    int ri0 = r0 + tr*2, ri1 = ri0 + 1;
    int fA = f0 + tf*2, fB2 = fA + 1;
    float bA = __ldg(&bout[fA]), bB = __ldg(&bout[fB2]);
    int m0 = g_mask[ri0], m1 = g_mask[ri1];
    g_y[(size_t)ri0*FB + fA ] = x[(size_t)ri0*FB + fA ] + (m0 ? (a00 + bA) : 0.f);
    g_y[(size_t)ri0*FB + fB2] = x[(size_t)ri0*FB + fB2] + (m0 ? (a01 + bB) : 0.f);
    g_y[(size_t)ri1*FB + fA ] = x[(size_t)ri1*FB + fA ] + (m1 ? (a10 + bA) : 0.f);
    g_y[(size_t)ri1*FB + fB2] = x[(size_t)ri1*FB + fB2] + (m1 ? (a11 + bB) : 0.f);
}

// ---------------------------------------------------------------------------
// D2: LayerNorm.
// ---------------------------------------------------------------------------
__global__ __launch_bounds__(256) void ln_kernel(
    const float* __restrict__ lnw,
    const float* __restrict__ lnb,
    float* __restrict__ out)
{
    int t = threadIdx.x;
    int wid = t >> 5, lane = t & 31;
    int ri = blockIdx.x * 8 + wid;
    const float* yr = g_y + (size_t)ri*FB;
    float v0 = yr[lane], v1 = yr[lane+32], v2 = yr[lane+64], v3 = yr[lane+96];
    float s = v0 + v1 + v2 + v3;
#pragma unroll
    for (int off = 16; off; off >>= 1) s += __shfl_xor_sync(0xffffffffu, s, off);
    float mu = s * (1.0f/128.0f);
    float d0 = v0-mu, d1 = v1-mu, d2 = v2-mu, d3 = v3-mu;
    float sq = d0*d0 + d1*d1 + d2*d2 + d3*d3;
#pragma unroll
    for (int off = 16; off; off >>= 1) sq += __shfl_xor_sync(0xffffffffu, sq, off);
    float rstd = rsqrtf(sq * (1.0f/128.0f) + 1e-5f);
    out[(size_t)ri*FB + lane     ] = d0*rstd*lnw[lane     ] + lnb[lane     ];
    out[(size_t)ri*FB + lane + 32] = d1*rstd*lnw[lane + 32] + lnb[lane + 32];
    out[(size_t)ri*FB + lane + 64] = d2*rstd*lnw[lane + 64] + lnb[lane + 64];
    out[(size_t)ri*FB + lane + 96] = d3*rstd*lnw[lane + 96] + lnb[lane + 96];
}

extern "C" void kernel_launch(void* const* d_in, const int* in_sizes, int n_in,
                              void* d_out, int out_size) {
    const float* R    = (const float*)d_in[0];
    const float* tv   = (const float*)d_in[1];
    const float* pCB  = (const float*)d_in[2];
    const float* x    = (const float*)d_in[3];
    const float* z    = (const float*)d_in[4];
    const void*  mask = d_in[5];
    const float* Wq   = (const float*)d_in[6];
    const float* Wk   = (const float*)d_in[7];
    const float* Wv   = (const float*)d_in[8];
    const float* Wpb  = (const float*)d_in[9];
    const float* gr   = (const float*)d_in[10];
    const float* Wout = (const float*)d_in[11];
    const float* bo   = (const float*)d_in[12];
    const float* lnw  = (const float*)d_in[13];
    const float* lnb  = (const float*)d_in[14];
    float* out = (float*)d_out;

    decode_mask_kernel<<<1, NL>>>(mask);
    prepw_kernel<<<FB, 256>>>(Wout);
    qkv_kernel<<<NL/8, 576>>>(x, Wq, Wk, Wv);
    qk_kernel<<<NH*64, 256>>>();
    fused_pz_kernel<<<NL, 256>>>(pCB, z, Wpb, gr);
    av_kernel<<<NH*8, 320>>>(pCB);
    spatial_kernel<<<NL*HB/256, 256>>>(R, tv);
    proj_kernel<<<128, 256>>>(x, bo);
    ln_kernel<<<NL/8, 256>>>(lnw, lnb, out);
}